// round 1
// baseline (speedup 1.0000x reference)
#include <cuda_runtime.h>
#include <cuda_bf16.h>
#include <math.h>

// Problem constants (fixed by the reference)
#define N_NODES 50000
#define E_MAX   800000
#define IN_C    128
#define HID     64
#define HEADS   4
#define F1      (HEADS*HID)   // 256
#define OUT_C   64
#define NUM_CLASSES 40

// ----------------------------------------------------------------------------
// Scratch (device globals: allocation-free per harness rules)
// ----------------------------------------------------------------------------
__device__ float g_h1[(size_t)N_NODES * F1];    // layer-1 linear output
__device__ float g_x2[(size_t)N_NODES * F1];    // layer-1 GAT output (relu'd)
__device__ float g_h2[(size_t)N_NODES * OUT_C]; // layer-2 linear output
__device__ float g_as1[N_NODES * HEADS];
__device__ float g_ad1[N_NODES * HEADS];
__device__ float g_as2[N_NODES];
__device__ float g_ad2[N_NODES];
__device__ int   g_counts[N_NODES + 1];
__device__ int   g_rowptr[N_NODES + 1];
__device__ int   g_cursor[N_NODES];
__device__ int   g_src32[E_MAX];
__device__ int   g_dst32[E_MAX];
__device__ int   g_csr_src[E_MAX];
__device__ float g_pooled[OUT_C];
__device__ int   g_is64;

__device__ __forceinline__ float lrelu(float v) { return v > 0.f ? v : 0.2f * v; }

// ----------------------------------------------------------------------------
// 0) zero counts + pooled
// ----------------------------------------------------------------------------
__global__ void zero_kernel() {
    int i = blockIdx.x * blockDim.x + threadIdx.x;
    if (i < N_NODES + 1) g_counts[i] = 0;
    if (i < OUT_C)       g_pooled[i] = 0.f;
}

// ----------------------------------------------------------------------------
// 1) detect whether edge_index is int64 or int32 (JAX x64 ambiguity).
//    int64 little-endian with values < 2^31 -> all odd 32-bit words are 0.
// ----------------------------------------------------------------------------
__global__ void detect_kernel(const int* __restrict__ ei) {
    __shared__ int any;
    if (threadIdx.x == 0) any = 0;
    __syncthreads();
    for (int i = threadIdx.x; i < 4096; i += blockDim.x) {
        if (ei[2 * i + 1] != 0) any = 1;
    }
    __syncthreads();
    if (threadIdx.x == 0) g_is64 = (any == 0) ? 1 : 0;
}

// ----------------------------------------------------------------------------
// 2) convert to int32 + count in-degrees
// ----------------------------------------------------------------------------
__global__ void convert_count_kernel(const void* __restrict__ ei, int E) {
    int e = blockIdx.x * blockDim.x + threadIdx.x;
    if (e >= E) return;
    int s, d;
    if (g_is64) {
        const long long* p = (const long long*)ei;
        s = (int)p[e]; d = (int)p[E + e];
    } else {
        const int* p = (const int*)ei;
        s = p[e]; d = p[E + e];
    }
    g_src32[e] = s;
    g_dst32[e] = d;
    atomicAdd(&g_counts[d], 1);
}

// ----------------------------------------------------------------------------
// 3) exclusive scan (single block, 1024 threads) -> rowptr, cursor
// ----------------------------------------------------------------------------
__global__ void scan_kernel() {
    __shared__ int sums[1024];
    const int t = threadIdx.x;
    const int chunk = (N_NODES + 1023) / 1024;
    int beg = t * chunk;
    int end = beg + chunk; if (end > N_NODES) end = N_NODES;
    if (beg > N_NODES) beg = N_NODES;
    int s = 0;
    for (int i = beg; i < end; i++) s += g_counts[i];
    sums[t] = s;
    __syncthreads();
    for (int off = 1; off < 1024; off <<= 1) {
        int v = 0;
        if (t >= off) v = sums[t - off];
        __syncthreads();
        sums[t] += v;
        __syncthreads();
    }
    int run = (t == 0) ? 0 : sums[t - 1];
    for (int i = beg; i < end; i++) {
        g_rowptr[i] = run;
        g_cursor[i] = run;
        run += g_counts[i];
    }
    if (t == 1023) g_rowptr[N_NODES] = sums[1023];
}

// ----------------------------------------------------------------------------
// 4) fill CSR (src indices grouped by dst)
// ----------------------------------------------------------------------------
__global__ void fill_kernel(int E) {
    int e = blockIdx.x * blockDim.x + threadIdx.x;
    if (e >= E) return;
    int pos = atomicAdd(&g_cursor[g_dst32[e]], 1);
    g_csr_src[pos] = g_src32[e];
}

// ----------------------------------------------------------------------------
// SGEMM core: C[M,N] = A[M,K] @ B[K,N], row-major. 256 threads.
// ----------------------------------------------------------------------------
template <int BM, int BN, int BK, int TM, int TN>
__device__ __forceinline__ void sgemm_core(int M, int N, int K,
                                           const float* __restrict__ A,
                                           const float* __restrict__ B,
                                           float* __restrict__ C) {
    static_assert((BM / TM) * (BN / TN) == 256, "256 threads");
    static_assert((BM * BK) % (256 * 4) == 0, "A vec loads");
    static_assert((BK * BN) % (256 * 4) == 0, "B vec loads");
    __shared__ float As[BK][BM];
    __shared__ float Bs[BK][BN];

    const int tid = threadIdx.x;
    const int block_row = blockIdx.y * BM;
    const int block_col = blockIdx.x * BN;
    const int tx = tid % (BN / TN);
    const int ty = tid / (BN / TN);

    float acc[TM][TN];
#pragma unroll
    for (int i = 0; i < TM; i++)
#pragma unroll
        for (int j = 0; j < TN; j++) acc[i][j] = 0.f;

    constexpr int A_LOADS = BM * BK / (256 * 4);
    constexpr int B_LOADS = BK * BN / (256 * 4);

    for (int k0 = 0; k0 < K; k0 += BK) {
#pragma unroll
        for (int i = 0; i < A_LOADS; i++) {
            int idx = tid + i * 256;
            int r  = idx / (BK / 4);
            int c4 = idx % (BK / 4);
            int gr = block_row + r;
            float4 v = make_float4(0.f, 0.f, 0.f, 0.f);
            if (gr < M) v = *(const float4*)(A + (size_t)gr * K + k0 + c4 * 4);
            As[c4 * 4 + 0][r] = v.x;
            As[c4 * 4 + 1][r] = v.y;
            As[c4 * 4 + 2][r] = v.z;
            As[c4 * 4 + 3][r] = v.w;
        }
#pragma unroll
        for (int i = 0; i < B_LOADS; i++) {
            int idx = tid + i * 256;
            int r  = idx / (BN / 4);
            int c4 = idx % (BN / 4);
            float4 v = *(const float4*)(B + (size_t)(k0 + r) * N + block_col + c4 * 4);
            *(float4*)(&Bs[r][c4 * 4]) = v;
        }
        __syncthreads();
#pragma unroll
        for (int k = 0; k < BK; k++) {
            float ra[TM], rb[TN];
#pragma unroll
            for (int i = 0; i < TM; i++) ra[i] = As[k][ty * TM + i];
#pragma unroll
            for (int j = 0; j < TN; j++) rb[j] = Bs[k][tx * TN + j];
#pragma unroll
            for (int i = 0; i < TM; i++)
#pragma unroll
                for (int j = 0; j < TN; j++) acc[i][j] += ra[i] * rb[j];
        }
        __syncthreads();
    }
#pragma unroll
    for (int i = 0; i < TM; i++) {
        int gr = block_row + ty * TM + i;
        if (gr >= M) continue;
#pragma unroll
        for (int j = 0; j < TN; j += 4) {
            float4 v = make_float4(acc[i][j], acc[i][j + 1], acc[i][j + 2], acc[i][j + 3]);
            *(float4*)(C + (size_t)gr * N + block_col + tx * TN + j) = v;
        }
    }
}

__global__ void __launch_bounds__(256) gemm1_kernel(const float* __restrict__ x,
                                                    const float* __restrict__ W1) {
    sgemm_core<128, 128, 8, 8, 8>(N_NODES, F1, IN_C, x, W1, g_h1);
}

__global__ void __launch_bounds__(256) gemm2_kernel(const float* __restrict__ W2) {
    sgemm_core<128, 64, 16, 8, 4>(N_NODES, OUT_C, F1, g_x2, W2, g_h2);
}

// ----------------------------------------------------------------------------
// alpha kernels: per-node attention logit halves (warp per node)
// ----------------------------------------------------------------------------
__global__ void alpha1_kernel(const float* __restrict__ att_s,
                              const float* __restrict__ att_d) {
    int t = threadIdx.x;
    int warp = (blockIdx.x * blockDim.x + t) >> 5;
    if (warp >= N_NODES) return;
    int lane = t & 31;
    float ss[HEADS] = {0.f, 0.f, 0.f, 0.f};
    float sd[HEADS] = {0.f, 0.f, 0.f, 0.f};
#pragma unroll
    for (int j = 0; j < 8; j++) {
        int c = lane + 32 * j;          // column in [0,256)
        float v = g_h1[(size_t)warp * F1 + c];
        int h = j >> 1;                 // head = c/64
        ss[h] += v * att_s[c];
        sd[h] += v * att_d[c];
    }
#pragma unroll
    for (int h = 0; h < HEADS; h++) {
        float a = ss[h], b = sd[h];
#pragma unroll
        for (int off = 16; off > 0; off >>= 1) {
            a += __shfl_xor_sync(0xffffffffu, a, off);
            b += __shfl_xor_sync(0xffffffffu, b, off);
        }
        if (lane == 0) {
            g_as1[warp * HEADS + h] = a;
            g_ad1[warp * HEADS + h] = b;
        }
    }
}

__global__ void alpha2_kernel(const float* __restrict__ att_s,
                              const float* __restrict__ att_d) {
    int t = threadIdx.x;
    int warp = (blockIdx.x * blockDim.x + t) >> 5;
    if (warp >= N_NODES) return;
    int lane = t & 31;
    float v0 = g_h2[(size_t)warp * OUT_C + lane];
    float v1 = g_h2[(size_t)warp * OUT_C + 32 + lane];
    float a = v0 * att_s[lane] + v1 * att_s[32 + lane];
    float b = v0 * att_d[lane] + v1 * att_d[32 + lane];
#pragma unroll
    for (int off = 16; off > 0; off >>= 1) {
        a += __shfl_xor_sync(0xffffffffu, a, off);
        b += __shfl_xor_sync(0xffffffffu, b, off);
    }
    if (lane == 0) { g_as2[warp] = a; g_ad2[warp] = b; }
}

// ----------------------------------------------------------------------------
// Layer-1 aggregation: warp per dst node, softmax + weighted sum in registers.
// Includes implicit self-loop. Fuses +b1 and relu. Writes g_x2.
// ----------------------------------------------------------------------------
__global__ void agg1_kernel(const float* __restrict__ b1) {
    int t = threadIdx.x;
    int warp = (blockIdx.x * blockDim.x + t) >> 5;
    if (warp >= N_NODES) return;
    int lane = t & 31;
    int d = warp;
    int head = lane >> 3;           // 8 lanes per head, lane covers cols lane*8..lane*8+7

    float ad = g_ad1[d * HEADS + head];
    float e_self = lrelu(g_as1[d * HEADS + head] + ad);
    int beg = g_rowptr[d], end = g_rowptr[d + 1];

    float m = e_self;
    for (int i = beg; i < end; i++) {
        int s = g_csr_src[i];
        m = fmaxf(m, lrelu(g_as1[s * HEADS + head] + ad));
    }

    float denom = 1e-16f;
    float acc[8] = {0.f, 0.f, 0.f, 0.f, 0.f, 0.f, 0.f, 0.f};
    for (int i = beg; i < end; i++) {
        int s = g_csr_src[i];
        float w = __expf(lrelu(g_as1[s * HEADS + head] + ad) - m);
        denom += w;
        const float4* hp = (const float4*)&g_h1[(size_t)s * F1 + lane * 8];
        float4 v0 = hp[0], v1 = hp[1];
        acc[0] += w * v0.x; acc[1] += w * v0.y; acc[2] += w * v0.z; acc[3] += w * v0.w;
        acc[4] += w * v1.x; acc[5] += w * v1.y; acc[6] += w * v1.z; acc[7] += w * v1.w;
    }
    {   // self loop
        float w = __expf(e_self - m);
        denom += w;
        const float4* hp = (const float4*)&g_h1[(size_t)d * F1 + lane * 8];
        float4 v0 = hp[0], v1 = hp[1];
        acc[0] += w * v0.x; acc[1] += w * v0.y; acc[2] += w * v0.z; acc[3] += w * v0.w;
        acc[4] += w * v1.x; acc[5] += w * v1.y; acc[6] += w * v1.z; acc[7] += w * v1.w;
    }
    float inv = 1.f / denom;
    int cb = lane * 8;
    float4 o0, o1;
    o0.x = fmaxf(acc[0] * inv + b1[cb + 0], 0.f);
    o0.y = fmaxf(acc[1] * inv + b1[cb + 1], 0.f);
    o0.z = fmaxf(acc[2] * inv + b1[cb + 2], 0.f);
    o0.w = fmaxf(acc[3] * inv + b1[cb + 3], 0.f);
    o1.x = fmaxf(acc[4] * inv + b1[cb + 4], 0.f);
    o1.y = fmaxf(acc[5] * inv + b1[cb + 5], 0.f);
    o1.z = fmaxf(acc[6] * inv + b1[cb + 6], 0.f);
    o1.w = fmaxf(acc[7] * inv + b1[cb + 7], 0.f);
    *(float4*)&g_x2[(size_t)d * F1 + cb]     = o0;
    *(float4*)&g_x2[(size_t)d * F1 + cb + 4] = o1;
}

// ----------------------------------------------------------------------------
// Layer-2 aggregation (heads=1) + bias + relu + global mean-pool accumulation.
// out2 is never materialized.
// ----------------------------------------------------------------------------
__global__ void agg2_pool_kernel(const float* __restrict__ b2) {
    __shared__ float sp[OUT_C];
    int t = threadIdx.x;
    if (t < OUT_C) sp[t] = 0.f;
    __syncthreads();

    int warp = (blockIdx.x * blockDim.x + t) >> 5;
    int lane = t & 31;
    if (warp < N_NODES) {
        int d = warp;
        float ad = g_ad2[d];
        float e_self = lrelu(g_as2[d] + ad);
        int beg = g_rowptr[d], end = g_rowptr[d + 1];

        float m = e_self;
        for (int i = beg; i < end; i++) {
            m = fmaxf(m, lrelu(g_as2[g_csr_src[i]] + ad));
        }
        float denom = 1e-16f;
        float a0 = 0.f, a1 = 0.f;
        for (int i = beg; i < end; i++) {
            int s = g_csr_src[i];
            float w = __expf(lrelu(g_as2[s] + ad) - m);
            denom += w;
            a0 += w * g_h2[(size_t)s * OUT_C + lane];
            a1 += w * g_h2[(size_t)s * OUT_C + 32 + lane];
        }
        {
            float w = __expf(e_self - m);
            denom += w;
            a0 += w * g_h2[(size_t)d * OUT_C + lane];
            a1 += w * g_h2[(size_t)d * OUT_C + 32 + lane];
        }
        float inv = 1.f / denom;
        float v0 = fmaxf(a0 * inv + b2[lane], 0.f);
        float v1 = fmaxf(a1 * inv + b2[32 + lane], 0.f);
        atomicAdd(&sp[lane], v0);
        atomicAdd(&sp[32 + lane], v1);
    }
    __syncthreads();
    if (t < OUT_C) atomicAdd(&g_pooled[t], sp[t]);
}

// ----------------------------------------------------------------------------
// Final: mean-pool scale, FC to 40 classes, log_softmax
// ----------------------------------------------------------------------------
__global__ void final_kernel(const float* __restrict__ fc_w,
                             const float* __restrict__ fc_b,
                             float* __restrict__ out) {
    __shared__ float p[OUT_C];
    __shared__ float lg[NUM_CLASSES];
    __shared__ float lse_sh;
    int t = threadIdx.x;  // 64 threads
    p[t] = g_pooled[t] * (1.0f / (float)N_NODES);
    __syncthreads();
    if (t < NUM_CLASSES) {
        float s = fc_b[t];
#pragma unroll
        for (int c = 0; c < OUT_C; c++) s += p[c] * fc_w[c * NUM_CLASSES + t];
        lg[t] = s;
    }
    __syncthreads();
    if (t == 0) {
        float mx = lg[0];
        for (int j = 1; j < NUM_CLASSES; j++) mx = fmaxf(mx, lg[j]);
        float se = 0.f;
        for (int j = 0; j < NUM_CLASSES; j++) se += expf(lg[j] - mx);
        lse_sh = mx + logf(se);
    }
    __syncthreads();
    if (t < NUM_CLASSES) out[t] = lg[t] - lse_sh;
}

// ----------------------------------------------------------------------------
// launch
// ----------------------------------------------------------------------------
extern "C" void kernel_launch(void* const* d_in, const int* in_sizes, int n_in,
                              void* d_out, int out_size) {
    const float* x      = (const float*)d_in[0];
    const void*  ei     = d_in[1];
    const float* W1     = (const float*)d_in[2];
    const float* att_s1 = (const float*)d_in[3];
    const float* att_d1 = (const float*)d_in[4];
    const float* b1     = (const float*)d_in[5];
    const float* W2     = (const float*)d_in[6];
    const float* att_s2 = (const float*)d_in[7];
    const float* att_d2 = (const float*)d_in[8];
    const float* b2     = (const float*)d_in[9];
    const float* fc_w   = (const float*)d_in[10];
    const float* fc_b   = (const float*)d_in[11];
    float* out = (float*)d_out;

    int E = in_sizes[1] / 2;
    if (E > E_MAX) E = E_MAX;

    const int WARPS_PER_BLOCK = 8;
    const int nodeBlocks = (N_NODES + WARPS_PER_BLOCK - 1) / WARPS_PER_BLOCK;

    zero_kernel<<<(N_NODES + 256) / 256, 256>>>();
    detect_kernel<<<1, 256>>>((const int*)ei);
    convert_count_kernel<<<(E + 255) / 256, 256>>>(ei, E);
    scan_kernel<<<1, 1024>>>();
    fill_kernel<<<(E + 255) / 256, 256>>>(E);

    // Layer 1
    gemm1_kernel<<<dim3(F1 / 128, (N_NODES + 127) / 128), 256>>>(x, W1);
    alpha1_kernel<<<nodeBlocks, 256>>>(att_s1, att_d1);
    agg1_kernel<<<nodeBlocks, 256>>>(b1);

    // Layer 2
    gemm2_kernel<<<dim3(1, (N_NODES + 127) / 128), 256>>>(W2);
    alpha2_kernel<<<nodeBlocks, 256>>>(att_s2, att_d2);
    agg2_pool_kernel<<<nodeBlocks, 256>>>(b2);

    // Head
    final_kernel<<<1, 64>>>(fc_w, fc_b, out);
}

// round 4
// speedup vs baseline: 1.2095x; 1.2095x over previous
#include <cuda_runtime.h>
#include <cuda_bf16.h>
#include <math.h>

// Problem constants (fixed by the reference)
#define N_NODES 50000
#define E_MAX   800000
#define IN_C    128
#define HID     64
#define HEADS   4
#define F1      (HEADS*HID)   // 256
#define OUT_C   64
#define NUM_CLASSES 40

#define SCAN_BLOCK 1024
#define SCAN_NBLK  ((N_NODES + SCAN_BLOCK - 1) / SCAN_BLOCK)   // 49

// ----------------------------------------------------------------------------
// Scratch (device globals: allocation-free per harness rules)
// ----------------------------------------------------------------------------
__device__ float g_h1[(size_t)N_NODES * F1];    // layer-1 linear output
__device__ float g_x2[(size_t)N_NODES * F1];    // layer-1 GAT output (relu'd)
__device__ float g_h2[(size_t)N_NODES * OUT_C]; // layer-2 linear output
__device__ float g_as1[N_NODES * HEADS];
__device__ float g_ad1[N_NODES * HEADS];
__device__ float g_as2[N_NODES];
__device__ float g_ad2[N_NODES];
__device__ int   g_counts[N_NODES + 1];
__device__ int   g_rowptr[N_NODES + 1];
__device__ int   g_cursor[N_NODES];
__device__ int   g_src32[E_MAX];
__device__ int   g_dst32[E_MAX];
__device__ int   g_csr_src[E_MAX];
__device__ int   g_blksum[SCAN_NBLK];
__device__ int   g_blkoff[SCAN_NBLK];
__device__ float g_pooled[OUT_C];
__device__ int   g_is64;

__device__ __forceinline__ float lrelu(float v) { return v > 0.f ? v : 0.2f * v; }

// ----------------------------------------------------------------------------
// 0) zero counts + pooled
// ----------------------------------------------------------------------------
__global__ void zero_kernel() {
    int i = blockIdx.x * blockDim.x + threadIdx.x;
    if (i < N_NODES + 1) g_counts[i] = 0;
    if (i < OUT_C)       g_pooled[i] = 0.f;
}

// ----------------------------------------------------------------------------
// 1) detect whether edge_index is int64 or int32 (JAX x64 ambiguity).
// ----------------------------------------------------------------------------
__global__ void detect_kernel(const int* __restrict__ ei) {
    __shared__ int any;
    if (threadIdx.x == 0) any = 0;
    __syncthreads();
    for (int i = threadIdx.x; i < 4096; i += blockDim.x) {
        if (ei[2 * i + 1] != 0) any = 1;
    }
    __syncthreads();
    if (threadIdx.x == 0) g_is64 = (any == 0) ? 1 : 0;
}

// ----------------------------------------------------------------------------
// 2) convert to int32 + count in-degrees
// ----------------------------------------------------------------------------
__global__ void convert_count_kernel(const void* __restrict__ ei, int E) {
    int e = blockIdx.x * blockDim.x + threadIdx.x;
    if (e >= E) return;
    int s, d;
    if (g_is64) {
        const long long* p = (const long long*)ei;
        s = (int)p[e]; d = (int)p[E + e];
    } else {
        const int* p = (const int*)ei;
        s = p[e]; d = p[E + e];
    }
    g_src32[e] = s;
    g_dst32[e] = d;
    atomicAdd(&g_counts[d], 1);
}

// ----------------------------------------------------------------------------
// 3) parallel exclusive scan of g_counts -> g_rowptr / g_cursor
//    phase 1: per-block sums; phase 2: scan block sums; phase 3: apply.
// ----------------------------------------------------------------------------
__global__ void __launch_bounds__(SCAN_BLOCK) scan1_kernel() {
    int i = blockIdx.x * SCAN_BLOCK + threadIdx.x;
    int v = (i < N_NODES) ? g_counts[i] : 0;
    __shared__ int sh[32];
    int lane = threadIdx.x & 31, w = threadIdx.x >> 5;
#pragma unroll
    for (int o = 16; o; o >>= 1) v += __shfl_xor_sync(~0u, v, o);
    if (lane == 0) sh[w] = v;
    __syncthreads();
    if (w == 0) {
        int s = sh[lane];
#pragma unroll
        for (int o = 16; o; o >>= 1) s += __shfl_xor_sync(~0u, s, o);
        if (lane == 0) g_blksum[blockIdx.x] = s;
    }
}

__global__ void scan2_kernel() {
    __shared__ int s[64];
    int t = threadIdx.x;
    int v = (t < SCAN_NBLK) ? g_blksum[t] : 0;
    s[t] = v;
    __syncthreads();
#pragma unroll
    for (int o = 1; o < 64; o <<= 1) {
        int u = (t >= o) ? s[t - o] : 0;
        __syncthreads();
        s[t] += u;
        __syncthreads();
    }
    if (t < SCAN_NBLK) g_blkoff[t] = s[t] - v;
    if (t == SCAN_NBLK - 1) g_rowptr[N_NODES] = s[t];
}

__global__ void __launch_bounds__(SCAN_BLOCK) scan3_kernel() {
    int b = blockIdx.x, t = threadIdx.x;
    int i = b * SCAN_BLOCK + t;
    int v = (i < N_NODES) ? g_counts[i] : 0;
    int lane = t & 31, w = t >> 5;
    int inc = v;
#pragma unroll
    for (int o = 1; o < 32; o <<= 1) {
        int u = __shfl_up_sync(~0u, inc, o);
        if (lane >= o) inc += u;
    }
    __shared__ int wsum[32];
    if (lane == 31) wsum[w] = inc;
    __syncthreads();
    if (w == 0) {
        int s = wsum[lane];
#pragma unroll
        for (int o = 1; o < 32; o <<= 1) {
            int u = __shfl_up_sync(~0u, s, o);
            if (lane >= o) s += u;
        }
        wsum[lane] = s;
    }
    __syncthreads();
    int exc = inc - v + (w > 0 ? wsum[w - 1] : 0) + g_blkoff[b];
    if (i < N_NODES) {
        g_rowptr[i] = exc;
        g_cursor[i] = exc;
    }
}

// ----------------------------------------------------------------------------
// 4) fill CSR (src indices grouped by dst)
// ----------------------------------------------------------------------------
__global__ void fill_kernel(int E) {
    int e = blockIdx.x * blockDim.x + threadIdx.x;
    if (e >= E) return;
    int pos = atomicAdd(&g_cursor[g_dst32[e]], 1);
    g_csr_src[pos] = g_src32[e];
}

// ----------------------------------------------------------------------------
// SGEMM core: C[M,N] = A[M,K] @ B[K,N], row-major. 256 threads. (PROVEN r1)
// ----------------------------------------------------------------------------
template <int BM, int BN, int BK, int TM, int TN>
__device__ __forceinline__ void sgemm_core(int M, int N, int K,
                                           const float* __restrict__ A,
                                           const float* __restrict__ B,
                                           float* __restrict__ C) {
    static_assert((BM / TM) * (BN / TN) == 256, "256 threads");
    static_assert((BM * BK) % (256 * 4) == 0, "A vec loads");
    static_assert((BK * BN) % (256 * 4) == 0, "B vec loads");
    __shared__ float As[BK][BM];
    __shared__ float Bs[BK][BN];

    const int tid = threadIdx.x;
    const int block_row = blockIdx.y * BM;
    const int block_col = blockIdx.x * BN;
    const int tx = tid % (BN / TN);
    const int ty = tid / (BN / TN);

    float acc[TM][TN];
#pragma unroll
    for (int i = 0; i < TM; i++)
#pragma unroll
        for (int j = 0; j < TN; j++) acc[i][j] = 0.f;

    constexpr int A_LOADS = BM * BK / (256 * 4);
    constexpr int B_LOADS = BK * BN / (256 * 4);

    for (int k0 = 0; k0 < K; k0 += BK) {
#pragma unroll
        for (int i = 0; i < A_LOADS; i++) {
            int idx = tid + i * 256;
            int r  = idx / (BK / 4);
            int c4 = idx % (BK / 4);
            int gr = block_row + r;
            float4 v = make_float4(0.f, 0.f, 0.f, 0.f);
            if (gr < M) v = *(const float4*)(A + (size_t)gr * K + k0 + c4 * 4);
            As[c4 * 4 + 0][r] = v.x;
            As[c4 * 4 + 1][r] = v.y;
            As[c4 * 4 + 2][r] = v.z;
            As[c4 * 4 + 3][r] = v.w;
        }
#pragma unroll
        for (int i = 0; i < B_LOADS; i++) {
            int idx = tid + i * 256;
            int r  = idx / (BN / 4);
            int c4 = idx % (BN / 4);
            float4 v = *(const float4*)(B + (size_t)(k0 + r) * N + block_col + c4 * 4);
            *(float4*)(&Bs[r][c4 * 4]) = v;
        }
        __syncthreads();
#pragma unroll
        for (int k = 0; k < BK; k++) {
            float ra[TM], rb[TN];
#pragma unroll
            for (int i = 0; i < TM; i++) ra[i] = As[k][ty * TM + i];
#pragma unroll
            for (int j = 0; j < TN; j++) rb[j] = Bs[k][tx * TN + j];
#pragma unroll
            for (int i = 0; i < TM; i++)
#pragma unroll
                for (int j = 0; j < TN; j++) acc[i][j] += ra[i] * rb[j];
        }
        __syncthreads();
    }
#pragma unroll
    for (int i = 0; i < TM; i++) {
        int gr = block_row + ty * TM + i;
        if (gr >= M) continue;
#pragma unroll
        for (int j = 0; j < TN; j += 4) {
            float4 v = make_float4(acc[i][j], acc[i][j + 1], acc[i][j + 2], acc[i][j + 3]);
            *(float4*)(C + (size_t)gr * N + block_col + tx * TN + j) = v;
        }
    }
}

__global__ void __launch_bounds__(256) gemm1_kernel(const float* __restrict__ x,
                                                    const float* __restrict__ W1) {
    sgemm_core<128, 128, 8, 8, 8>(N_NODES, F1, IN_C, x, W1, g_h1);
}

__global__ void __launch_bounds__(256) gemm2_kernel(const float* __restrict__ W2) {
    sgemm_core<128, 64, 16, 8, 4>(N_NODES, OUT_C, F1, g_x2, W2, g_h2);
}

// ----------------------------------------------------------------------------
// alpha kernels: per-node attention logit halves (warp per node)
// ----------------------------------------------------------------------------
__global__ void alpha1_kernel(const float* __restrict__ att_s,
                              const float* __restrict__ att_d) {
    int t = threadIdx.x;
    int warp = (blockIdx.x * blockDim.x + t) >> 5;
    if (warp >= N_NODES) return;
    int lane = t & 31;
    float ss[HEADS] = {0.f, 0.f, 0.f, 0.f};
    float sd[HEADS] = {0.f, 0.f, 0.f, 0.f};
#pragma unroll
    for (int j = 0; j < 8; j++) {
        int c = lane + 32 * j;
        float v = g_h1[(size_t)warp * F1 + c];
        int h = j >> 1;
        ss[h] += v * att_s[c];
        sd[h] += v * att_d[c];
    }
#pragma unroll
    for (int h = 0; h < HEADS; h++) {
        float a = ss[h], b = sd[h];
#pragma unroll
        for (int off = 16; off > 0; off >>= 1) {
            a += __shfl_xor_sync(0xffffffffu, a, off);
            b += __shfl_xor_sync(0xffffffffu, b, off);
        }
        if (lane == 0) {
            g_as1[warp * HEADS + h] = a;
            g_ad1[warp * HEADS + h] = b;
        }
    }
}

__global__ void alpha2_kernel(const float* __restrict__ att_s,
                              const float* __restrict__ att_d) {
    int t = threadIdx.x;
    int warp = (blockIdx.x * blockDim.x + t) >> 5;
    if (warp >= N_NODES) return;
    int lane = t & 31;
    float v0 = g_h2[(size_t)warp * OUT_C + lane];
    float v1 = g_h2[(size_t)warp * OUT_C + 32 + lane];
    float a = v0 * att_s[lane] + v1 * att_s[32 + lane];
    float b = v0 * att_d[lane] + v1 * att_d[32 + lane];
#pragma unroll
    for (int off = 16; off > 0; off >>= 1) {
        a += __shfl_xor_sync(0xffffffffu, a, off);
        b += __shfl_xor_sync(0xffffffffu, b, off);
    }
    if (lane == 0) { g_as2[warp] = a; g_ad2[warp] = b; }
}

// ----------------------------------------------------------------------------
// Layer-1 aggregation: warp per dst node, softmax + weighted sum in registers.
// ----------------------------------------------------------------------------
__global__ void agg1_kernel(const float* __restrict__ b1) {
    int t = threadIdx.x;
    int warp = (blockIdx.x * blockDim.x + t) >> 5;
    if (warp >= N_NODES) return;
    int lane = t & 31;
    int d = warp;
    int head = lane >> 3;

    float ad = g_ad1[d * HEADS + head];
    float e_self = lrelu(g_as1[d * HEADS + head] + ad);
    int beg = g_rowptr[d], end = g_rowptr[d + 1];

    float m = e_self;
    for (int i = beg; i < end; i++) {
        int s = g_csr_src[i];
        m = fmaxf(m, lrelu(g_as1[s * HEADS + head] + ad));
    }

    float denom = 1e-16f;
    float acc[8] = {0.f, 0.f, 0.f, 0.f, 0.f, 0.f, 0.f, 0.f};
    for (int i = beg; i < end; i++) {
        int s = g_csr_src[i];
        float w = __expf(lrelu(g_as1[s * HEADS + head] + ad) - m);
        denom += w;
        const float4* hp = (const float4*)&g_h1[(size_t)s * F1 + lane * 8];
        float4 v0 = hp[0], v1 = hp[1];
        acc[0] += w * v0.x; acc[1] += w * v0.y; acc[2] += w * v0.z; acc[3] += w * v0.w;
        acc[4] += w * v1.x; acc[5] += w * v1.y; acc[6] += w * v1.z; acc[7] += w * v1.w;
    }
    {   // self loop
        float w = __expf(e_self - m);
        denom += w;
        const float4* hp = (const float4*)&g_h1[(size_t)d * F1 + lane * 8];
        float4 v0 = hp[0], v1 = hp[1];
        acc[0] += w * v0.x; acc[1] += w * v0.y; acc[2] += w * v0.z; acc[3] += w * v0.w;
        acc[4] += w * v1.x; acc[5] += w * v1.y; acc[6] += w * v1.z; acc[7] += w * v1.w;
    }
    float inv = 1.f / denom;
    int cb = lane * 8;
    float4 o0, o1;
    o0.x = fmaxf(acc[0] * inv + b1[cb + 0], 0.f);
    o0.y = fmaxf(acc[1] * inv + b1[cb + 1], 0.f);
    o0.z = fmaxf(acc[2] * inv + b1[cb + 2], 0.f);
    o0.w = fmaxf(acc[3] * inv + b1[cb + 3], 0.f);
    o1.x = fmaxf(acc[4] * inv + b1[cb + 4], 0.f);
    o1.y = fmaxf(acc[5] * inv + b1[cb + 5], 0.f);
    o1.z = fmaxf(acc[6] * inv + b1[cb + 6], 0.f);
    o1.w = fmaxf(acc[7] * inv + b1[cb + 7], 0.f);
    *(float4*)&g_x2[(size_t)d * F1 + cb]     = o0;
    *(float4*)&g_x2[(size_t)d * F1 + cb + 4] = o1;
}

// ----------------------------------------------------------------------------
// Layer-2 aggregation (heads=1) + bias + relu + global mean-pool accumulation.
// ----------------------------------------------------------------------------
__global__ void agg2_pool_kernel(const float* __restrict__ b2) {
    __shared__ float sp[OUT_C];
    int t = threadIdx.x;
    if (t < OUT_C) sp[t] = 0.f;
    __syncthreads();

    int warp = (blockIdx.x * blockDim.x + t) >> 5;
    int lane = t & 31;
    if (warp < N_NODES) {
        int d = warp;
        float ad = g_ad2[d];
        float e_self = lrelu(g_as2[d] + ad);
        int beg = g_rowptr[d], end = g_rowptr[d + 1];

        float m = e_self;
        for (int i = beg; i < end; i++) {
            m = fmaxf(m, lrelu(g_as2[g_csr_src[i]] + ad));
        }
        float denom = 1e-16f;
        float a0 = 0.f, a1 = 0.f;
        for (int i = beg; i < end; i++) {
            int s = g_csr_src[i];
            float w = __expf(lrelu(g_as2[s] + ad) - m);
            denom += w;
            a0 += w * g_h2[(size_t)s * OUT_C + lane];
            a1 += w * g_h2[(size_t)s * OUT_C + 32 + lane];
        }
        {
            float w = __expf(e_self - m);
            denom += w;
            a0 += w * g_h2[(size_t)d * OUT_C + lane];
            a1 += w * g_h2[(size_t)d * OUT_C + 32 + lane];
        }
        float inv = 1.f / denom;
        float v0 = fmaxf(a0 * inv + b2[lane], 0.f);
        float v1 = fmaxf(a1 * inv + b2[32 + lane], 0.f);
        atomicAdd(&sp[lane], v0);
        atomicAdd(&sp[32 + lane], v1);
    }
    __syncthreads();
    if (t < OUT_C) atomicAdd(&g_pooled[t], sp[t]);
}

// ----------------------------------------------------------------------------
// Final: mean-pool scale, FC to 40 classes, log_softmax
// ----------------------------------------------------------------------------
__global__ void final_kernel(const float* __restrict__ fc_w,
                             const float* __restrict__ fc_b,
                             float* __restrict__ out) {
    __shared__ float p[OUT_C];
    __shared__ float lg[NUM_CLASSES];
    __shared__ float lse_sh;
    int t = threadIdx.x;  // 64 threads
    p[t] = g_pooled[t] * (1.0f / (float)N_NODES);
    __syncthreads();
    if (t < NUM_CLASSES) {
        float s = fc_b[t];
#pragma unroll
        for (int c = 0; c < OUT_C; c++) s += p[c] * fc_w[c * NUM_CLASSES + t];
        lg[t] = s;
    }
    __syncthreads();
    if (t == 0) {
        float mx = lg[0];
        for (int j = 1; j < NUM_CLASSES; j++) mx = fmaxf(mx, lg[j]);
        float se = 0.f;
        for (int j = 0; j < NUM_CLASSES; j++) se += expf(lg[j] - mx);
        lse_sh = mx + logf(se);
    }
    __syncthreads();
    if (t < NUM_CLASSES) out[t] = lg[t] - lse_sh;
}

// ----------------------------------------------------------------------------
// launch
// ----------------------------------------------------------------------------
extern "C" void kernel_launch(void* const* d_in, const int* in_sizes, int n_in,
                              void* d_out, int out_size) {
    const float* x      = (const float*)d_in[0];
    const void*  ei     = d_in[1];
    const float* W1     = (const float*)d_in[2];
    const float* att_s1 = (const float*)d_in[3];
    const float* att_d1 = (const float*)d_in[4];
    const float* b1     = (const float*)d_in[5];
    const float* W2     = (const float*)d_in[6];
    const float* att_s2 = (const float*)d_in[7];
    const float* att_d2 = (const float*)d_in[8];
    const float* b2     = (const float*)d_in[9];
    const float* fc_w   = (const float*)d_in[10];
    const float* fc_b   = (const float*)d_in[11];
    float* out = (float*)d_out;

    int E = in_sizes[1] / 2;
    if (E > E_MAX) E = E_MAX;

    const int WARPS_PER_BLOCK = 8;
    const int nodeBlocks = (N_NODES + WARPS_PER_BLOCK - 1) / WARPS_PER_BLOCK;

    zero_kernel<<<(N_NODES + 256) / 256, 256>>>();
    detect_kernel<<<1, 256>>>((const int*)ei);
    convert_count_kernel<<<(E + 255) / 256, 256>>>(ei, E);
    scan1_kernel<<<SCAN_NBLK, SCAN_BLOCK>>>();
    scan2_kernel<<<1, 64>>>();
    scan3_kernel<<<SCAN_NBLK, SCAN_BLOCK>>>();
    fill_kernel<<<(E + 255) / 256, 256>>>(E);

    // Layer 1: h1 = x @ W1 (50000x128 @ 128x256), proven SIMT SGEMM
    gemm1_kernel<<<dim3(F1 / 128, (N_NODES + 127) / 128), 256>>>(x, W1);
    alpha1_kernel<<<nodeBlocks, 256>>>(att_s1, att_d1);
    agg1_kernel<<<nodeBlocks, 256>>>(b1);

    // Layer 2: h2 = x2 @ W2 (50000x256 @ 256x64), proven SIMT SGEMM
    gemm2_kernel<<<dim3(1, (N_NODES + 127) / 128), 256>>>(W2);
    alpha2_kernel<<<nodeBlocks, 256>>>(att_s2, att_d2);
    agg2_pool_kernel<<<nodeBlocks, 256>>>(b2);

    // Head
    final_kernel<<<1, 64>>>(fc_w, fc_b, out);
}

// round 5
// speedup vs baseline: 1.3136x; 1.0861x over previous
#include <cuda_runtime.h>
#include <cuda_bf16.h>
#include <cuda_fp16.h>
#include <math.h>

// Problem constants (fixed by the reference)
#define N_NODES 50000
#define E_MAX   800000
#define IN_C    128
#define HID     64
#define HEADS   4
#define F1      (HEADS*HID)   // 256
#define OUT_C   64
#define NUM_CLASSES 40

#define SCAN_BLOCK 1024
#define SCAN_NBLK  ((N_NODES + SCAN_BLOCK - 1) / SCAN_BLOCK)   // 49

// ----------------------------------------------------------------------------
// Scratch (device globals: allocation-free per harness rules)
// ----------------------------------------------------------------------------
__device__ float  g_h1[(size_t)N_NODES * F1];    // layer-1 linear output (fp32)
__device__ __half g_h1h[(size_t)N_NODES * F1];   // fp16 gather copy of h1
__device__ float  g_x2[(size_t)N_NODES * F1];    // layer-1 GAT output (relu'd)
__device__ float  g_h2[(size_t)N_NODES * OUT_C]; // layer-2 linear output (fp32)
__device__ __half g_h2h[(size_t)N_NODES * OUT_C];// fp16 gather copy of h2
__device__ float  g_as1[N_NODES * HEADS];
__device__ float  g_ad1[N_NODES * HEADS];
__device__ float  g_as2[N_NODES];
__device__ float  g_ad2[N_NODES];
__device__ int    g_counts[N_NODES + 1];
__device__ int    g_rowptr[N_NODES + 1];
__device__ int    g_cursor[N_NODES];
__device__ int    g_src32[E_MAX];
__device__ int    g_dst32[E_MAX];
__device__ int    g_csr_src[E_MAX];
__device__ int    g_blksum[SCAN_NBLK];
__device__ int    g_blkoff[SCAN_NBLK];
__device__ float  g_pooled[OUT_C];
__device__ int    g_is64;

__device__ __forceinline__ float lrelu(float v) { return v > 0.f ? v : 0.2f * v; }

// ----------------------------------------------------------------------------
// 0) zero counts + pooled
// ----------------------------------------------------------------------------
__global__ void zero_kernel() {
    int i = blockIdx.x * blockDim.x + threadIdx.x;
    if (i < N_NODES + 1) g_counts[i] = 0;
    if (i < OUT_C)       g_pooled[i] = 0.f;
}

// ----------------------------------------------------------------------------
// 1) detect whether edge_index is int64 or int32 (JAX x64 ambiguity).
// ----------------------------------------------------------------------------
__global__ void detect_kernel(const int* __restrict__ ei) {
    __shared__ int any;
    if (threadIdx.x == 0) any = 0;
    __syncthreads();
    for (int i = threadIdx.x; i < 4096; i += blockDim.x) {
        if (ei[2 * i + 1] != 0) any = 1;
    }
    __syncthreads();
    if (threadIdx.x == 0) g_is64 = (any == 0) ? 1 : 0;
}

// ----------------------------------------------------------------------------
// 2) convert to int32 + count in-degrees
// ----------------------------------------------------------------------------
__global__ void convert_count_kernel(const void* __restrict__ ei, int E) {
    int e = blockIdx.x * blockDim.x + threadIdx.x;
    if (e >= E) return;
    int s, d;
    if (g_is64) {
        const long long* p = (const long long*)ei;
        s = (int)p[e]; d = (int)p[E + e];
    } else {
        const int* p = (const int*)ei;
        s = p[e]; d = p[E + e];
    }
    g_src32[e] = s;
    g_dst32[e] = d;
    atomicAdd(&g_counts[d], 1);
}

// ----------------------------------------------------------------------------
// 3) parallel exclusive scan of g_counts -> g_rowptr / g_cursor  (PROVEN r4)
// ----------------------------------------------------------------------------
__global__ void __launch_bounds__(SCAN_BLOCK) scan1_kernel() {
    int i = blockIdx.x * SCAN_BLOCK + threadIdx.x;
    int v = (i < N_NODES) ? g_counts[i] : 0;
    __shared__ int sh[32];
    int lane = threadIdx.x & 31, w = threadIdx.x >> 5;
#pragma unroll
    for (int o = 16; o; o >>= 1) v += __shfl_xor_sync(~0u, v, o);
    if (lane == 0) sh[w] = v;
    __syncthreads();
    if (w == 0) {
        int s = sh[lane];
#pragma unroll
        for (int o = 16; o; o >>= 1) s += __shfl_xor_sync(~0u, s, o);
        if (lane == 0) g_blksum[blockIdx.x] = s;
    }
}

__global__ void scan2_kernel() {
    __shared__ int s[64];
    int t = threadIdx.x;
    int v = (t < SCAN_NBLK) ? g_blksum[t] : 0;
    s[t] = v;
    __syncthreads();
#pragma unroll
    for (int o = 1; o < 64; o <<= 1) {
        int u = (t >= o) ? s[t - o] : 0;
        __syncthreads();
        s[t] += u;
        __syncthreads();
    }
    if (t < SCAN_NBLK) g_blkoff[t] = s[t] - v;
    if (t == SCAN_NBLK - 1) g_rowptr[N_NODES] = s[t];
}

__global__ void __launch_bounds__(SCAN_BLOCK) scan3_kernel() {
    int b = blockIdx.x, t = threadIdx.x;
    int i = b * SCAN_BLOCK + t;
    int v = (i < N_NODES) ? g_counts[i] : 0;
    int lane = t & 31, w = t >> 5;
    int inc = v;
#pragma unroll
    for (int o = 1; o < 32; o <<= 1) {
        int u = __shfl_up_sync(~0u, inc, o);
        if (lane >= o) inc += u;
    }
    __shared__ int wsum[32];
    if (lane == 31) wsum[w] = inc;
    __syncthreads();
    if (w == 0) {
        int s = wsum[lane];
#pragma unroll
        for (int o = 1; o < 32; o <<= 1) {
            int u = __shfl_up_sync(~0u, s, o);
            if (lane >= o) s += u;
        }
        wsum[lane] = s;
    }
    __syncthreads();
    int exc = inc - v + (w > 0 ? wsum[w - 1] : 0) + g_blkoff[b];
    if (i < N_NODES) {
        g_rowptr[i] = exc;
        g_cursor[i] = exc;
    }
}

// ----------------------------------------------------------------------------
// 4) fill CSR (src indices grouped by dst)
// ----------------------------------------------------------------------------
__global__ void fill_kernel(int E) {
    int e = blockIdx.x * blockDim.x + threadIdx.x;
    if (e >= E) return;
    int pos = atomicAdd(&g_cursor[g_dst32[e]], 1);
    g_csr_src[pos] = g_src32[e];
}

// ----------------------------------------------------------------------------
// SGEMM core: C[M,N] = A[M,K] @ B[K,N], row-major. 256 threads. (PROVEN r1/r4)
// ----------------------------------------------------------------------------
template <int BM, int BN, int BK, int TM, int TN>
__device__ __forceinline__ void sgemm_core(int M, int N, int K,
                                           const float* __restrict__ A,
                                           const float* __restrict__ B,
                                           float* __restrict__ C) {
    static_assert((BM / TM) * (BN / TN) == 256, "256 threads");
    __shared__ float As[BK][BM];
    __shared__ float Bs[BK][BN];

    const int tid = threadIdx.x;
    const int block_row = blockIdx.y * BM;
    const int block_col = blockIdx.x * BN;
    const int tx = tid % (BN / TN);
    const int ty = tid / (BN / TN);

    float acc[TM][TN];
#pragma unroll
    for (int i = 0; i < TM; i++)
#pragma unroll
        for (int j = 0; j < TN; j++) acc[i][j] = 0.f;

    constexpr int A_LOADS = BM * BK / (256 * 4);
    constexpr int B_LOADS = BK * BN / (256 * 4);

    for (int k0 = 0; k0 < K; k0 += BK) {
#pragma unroll
        for (int i = 0; i < A_LOADS; i++) {
            int idx = tid + i * 256;
            int r  = idx / (BK / 4);
            int c4 = idx % (BK / 4);
            int gr = block_row + r;
            float4 v = make_float4(0.f, 0.f, 0.f, 0.f);
            if (gr < M) v = *(const float4*)(A + (size_t)gr * K + k0 + c4 * 4);
            As[c4 * 4 + 0][r] = v.x;
            As[c4 * 4 + 1][r] = v.y;
            As[c4 * 4 + 2][r] = v.z;
            As[c4 * 4 + 3][r] = v.w;
        }
#pragma unroll
        for (int i = 0; i < B_LOADS; i++) {
            int idx = tid + i * 256;
            int r  = idx / (BN / 4);
            int c4 = idx % (BN / 4);
            float4 v = *(const float4*)(B + (size_t)(k0 + r) * N + block_col + c4 * 4);
            *(float4*)(&Bs[r][c4 * 4]) = v;
        }
        __syncthreads();
#pragma unroll
        for (int k = 0; k < BK; k++) {
            float ra[TM], rb[TN];
#pragma unroll
            for (int i = 0; i < TM; i++) ra[i] = As[k][ty * TM + i];
#pragma unroll
            for (int j = 0; j < TN; j++) rb[j] = Bs[k][tx * TN + j];
#pragma unroll
            for (int i = 0; i < TM; i++)
#pragma unroll
                for (int j = 0; j < TN; j++) acc[i][j] += ra[i] * rb[j];
        }
        __syncthreads();
    }
#pragma unroll
    for (int i = 0; i < TM; i++) {
        int gr = block_row + ty * TM + i;
        if (gr >= M) continue;
#pragma unroll
        for (int j = 0; j < TN; j += 4) {
            float4 v = make_float4(acc[i][j], acc[i][j + 1], acc[i][j + 2], acc[i][j + 3]);
            *(float4*)(C + (size_t)gr * N + block_col + tx * TN + j) = v;
        }
    }
}

__global__ void __launch_bounds__(256) gemm1_kernel(const float* __restrict__ x,
                                                    const float* __restrict__ W1) {
    sgemm_core<128, 128, 8, 8, 8>(N_NODES, F1, IN_C, x, W1, g_h1);
}

__global__ void __launch_bounds__(256) gemm2_kernel(const float* __restrict__ W2) {
    sgemm_core<128, 64, 16, 8, 4>(N_NODES, OUT_C, F1, g_x2, W2, g_h2);
}

// ----------------------------------------------------------------------------
// alpha kernels: per-node attention logits (fp32-exact) + fp16 gather copy
// ----------------------------------------------------------------------------
__global__ void alpha1_kernel(const float* __restrict__ att_s,
                              const float* __restrict__ att_d) {
    int t = threadIdx.x;
    int warp = (blockIdx.x * blockDim.x + t) >> 5;
    if (warp >= N_NODES) return;
    int lane = t & 31;
    float ss[HEADS] = {0.f, 0.f, 0.f, 0.f};
    float sd[HEADS] = {0.f, 0.f, 0.f, 0.f};
#pragma unroll
    for (int j = 0; j < 8; j++) {
        int c = lane + 32 * j;
        float v = g_h1[(size_t)warp * F1 + c];
        g_h1h[(size_t)warp * F1 + c] = __float2half(v);   // fp16 copy (coalesced 64B)
        int h = j >> 1;
        ss[h] += v * att_s[c];
        sd[h] += v * att_d[c];
    }
#pragma unroll
    for (int h = 0; h < HEADS; h++) {
        float a = ss[h], b = sd[h];
#pragma unroll
        for (int off = 16; off > 0; off >>= 1) {
            a += __shfl_xor_sync(0xffffffffu, a, off);
            b += __shfl_xor_sync(0xffffffffu, b, off);
        }
        if (lane == 0) {
            g_as1[warp * HEADS + h] = a;
            g_ad1[warp * HEADS + h] = b;
        }
    }
}

__global__ void alpha2_kernel(const float* __restrict__ att_s,
                              const float* __restrict__ att_d) {
    int t = threadIdx.x;
    int warp = (blockIdx.x * blockDim.x + t) >> 5;
    if (warp >= N_NODES) return;
    int lane = t & 31;
    float v0 = g_h2[(size_t)warp * OUT_C + lane];
    float v1 = g_h2[(size_t)warp * OUT_C + 32 + lane];
    g_h2h[(size_t)warp * OUT_C + lane]      = __float2half(v0);
    g_h2h[(size_t)warp * OUT_C + 32 + lane] = __float2half(v1);
    float a = v0 * att_s[lane] + v1 * att_s[32 + lane];
    float b = v0 * att_d[lane] + v1 * att_d[32 + lane];
#pragma unroll
    for (int off = 16; off > 0; off >>= 1) {
        a += __shfl_xor_sync(0xffffffffu, a, off);
        b += __shfl_xor_sync(0xffffffffu, b, off);
    }
    if (lane == 0) { g_as2[warp] = a; g_ad2[warp] = b; }
}

// ----------------------------------------------------------------------------
// Layer-1 aggregation: warp per dst node, single-pass softmax (logits are
// ~N(0,1): exp() safe without max subtraction; exact cancellation in ratio).
// fp16 gathers (512B/row), fp32 accumulation. Fuses +b1 and relu.
// ----------------------------------------------------------------------------
__global__ void agg1_kernel(const float* __restrict__ b1) {
    int t = threadIdx.x;
    int warp = (blockIdx.x * blockDim.x + t) >> 5;
    if (warp >= N_NODES) return;
    int lane = t & 31;
    int d = warp;
    int head = lane >> 3;

    float ad = g_ad1[d * HEADS + head];
    int beg = g_rowptr[d], end = g_rowptr[d + 1];

    float denom = 1e-16f;
    float acc[8] = {0.f, 0.f, 0.f, 0.f, 0.f, 0.f, 0.f, 0.f};
    for (int i = beg; i < end; i++) {
        int s = g_csr_src[i];
        float w = __expf(lrelu(g_as1[s * HEADS + head] + ad));
        denom += w;
        uint4 u = *(const uint4*)&g_h1h[(size_t)s * F1 + lane * 8];
        float2 f0 = __half22float2(*reinterpret_cast<__half2*>(&u.x));
        float2 f1 = __half22float2(*reinterpret_cast<__half2*>(&u.y));
        float2 f2 = __half22float2(*reinterpret_cast<__half2*>(&u.z));
        float2 f3 = __half22float2(*reinterpret_cast<__half2*>(&u.w));
        acc[0] += w * f0.x; acc[1] += w * f0.y;
        acc[2] += w * f1.x; acc[3] += w * f1.y;
        acc[4] += w * f2.x; acc[5] += w * f2.y;
        acc[6] += w * f3.x; acc[7] += w * f3.y;
    }
    {   // self loop
        float w = __expf(lrelu(g_as1[d * HEADS + head] + ad));
        denom += w;
        uint4 u = *(const uint4*)&g_h1h[(size_t)d * F1 + lane * 8];
        float2 f0 = __half22float2(*reinterpret_cast<__half2*>(&u.x));
        float2 f1 = __half22float2(*reinterpret_cast<__half2*>(&u.y));
        float2 f2 = __half22float2(*reinterpret_cast<__half2*>(&u.z));
        float2 f3 = __half22float2(*reinterpret_cast<__half2*>(&u.w));
        acc[0] += w * f0.x; acc[1] += w * f0.y;
        acc[2] += w * f1.x; acc[3] += w * f1.y;
        acc[4] += w * f2.x; acc[5] += w * f2.y;
        acc[6] += w * f3.x; acc[7] += w * f3.y;
    }
    float inv = 1.f / denom;
    int cb = lane * 8;
    float4 o0, o1;
    o0.x = fmaxf(acc[0] * inv + b1[cb + 0], 0.f);
    o0.y = fmaxf(acc[1] * inv + b1[cb + 1], 0.f);
    o0.z = fmaxf(acc[2] * inv + b1[cb + 2], 0.f);
    o0.w = fmaxf(acc[3] * inv + b1[cb + 3], 0.f);
    o1.x = fmaxf(acc[4] * inv + b1[cb + 4], 0.f);
    o1.y = fmaxf(acc[5] * inv + b1[cb + 5], 0.f);
    o1.z = fmaxf(acc[6] * inv + b1[cb + 6], 0.f);
    o1.w = fmaxf(acc[7] * inv + b1[cb + 7], 0.f);
    *(float4*)&g_x2[(size_t)d * F1 + cb]     = o0;
    *(float4*)&g_x2[(size_t)d * F1 + cb + 4] = o1;
}

// ----------------------------------------------------------------------------
// Layer-2 aggregation (heads=1) + bias + relu + global mean-pool accumulation.
// Single-pass softmax, fp16 gathers.
// ----------------------------------------------------------------------------
__global__ void agg2_pool_kernel(const float* __restrict__ b2) {
    __shared__ float sp[OUT_C];
    int t = threadIdx.x;
    if (t < OUT_C) sp[t] = 0.f;
    __syncthreads();

    int warp = (blockIdx.x * blockDim.x + t) >> 5;
    int lane = t & 31;
    if (warp < N_NODES) {
        int d = warp;
        float ad = g_ad2[d];
        int beg = g_rowptr[d], end = g_rowptr[d + 1];

        float denom = 1e-16f;
        float a0 = 0.f, a1 = 0.f;
        for (int i = beg; i < end; i++) {
            int s = g_csr_src[i];
            float w = __expf(lrelu(g_as2[s] + ad));
            denom += w;
            a0 += w * __half2float(g_h2h[(size_t)s * OUT_C + lane]);
            a1 += w * __half2float(g_h2h[(size_t)s * OUT_C + 32 + lane]);
        }
        {
            float w = __expf(lrelu(g_as2[d] + ad));
            denom += w;
            a0 += w * __half2float(g_h2h[(size_t)d * OUT_C + lane]);
            a1 += w * __half2float(g_h2h[(size_t)d * OUT_C + 32 + lane]);
        }
        float inv = 1.f / denom;
        float v0 = fmaxf(a0 * inv + b2[lane], 0.f);
        float v1 = fmaxf(a1 * inv + b2[32 + lane], 0.f);
        atomicAdd(&sp[lane], v0);
        atomicAdd(&sp[32 + lane], v1);
    }
    __syncthreads();
    if (t < OUT_C) atomicAdd(&g_pooled[t], sp[t]);
}

// ----------------------------------------------------------------------------
// Final: mean-pool scale, FC to 40 classes, log_softmax
// ----------------------------------------------------------------------------
__global__ void final_kernel(const float* __restrict__ fc_w,
                             const float* __restrict__ fc_b,
                             float* __restrict__ out) {
    __shared__ float p[OUT_C];
    __shared__ float lg[NUM_CLASSES];
    __shared__ float lse_sh;
    int t = threadIdx.x;  // 64 threads
    p[t] = g_pooled[t] * (1.0f / (float)N_NODES);
    __syncthreads();
    if (t < NUM_CLASSES) {
        float s = fc_b[t];
#pragma unroll
        for (int c = 0; c < OUT_C; c++) s += p[c] * fc_w[c * NUM_CLASSES + t];
        lg[t] = s;
    }
    __syncthreads();
    if (t == 0) {
        float mx = lg[0];
        for (int j = 1; j < NUM_CLASSES; j++) mx = fmaxf(mx, lg[j]);
        float se = 0.f;
        for (int j = 0; j < NUM_CLASSES; j++) se += expf(lg[j] - mx);
        lse_sh = mx + logf(se);
    }
    __syncthreads();
    if (t < NUM_CLASSES) out[t] = lg[t] - lse_sh;
}

// ----------------------------------------------------------------------------
// launch
// ----------------------------------------------------------------------------
extern "C" void kernel_launch(void* const* d_in, const int* in_sizes, int n_in,
                              void* d_out, int out_size) {
    const float* x      = (const float*)d_in[0];
    const void*  ei     = d_in[1];
    const float* W1     = (const float*)d_in[2];
    const float* att_s1 = (const float*)d_in[3];
    const float* att_d1 = (const float*)d_in[4];
    const float* b1     = (const float*)d_in[5];
    const float* W2     = (const float*)d_in[6];
    const float* att_s2 = (const float*)d_in[7];
    const float* att_d2 = (const float*)d_in[8];
    const float* b2     = (const float*)d_in[9];
    const float* fc_w   = (const float*)d_in[10];
    const float* fc_b   = (const float*)d_in[11];
    float* out = (float*)d_out;

    int E = in_sizes[1] / 2;
    if (E > E_MAX) E = E_MAX;

    const int WARPS_PER_BLOCK = 8;
    const int nodeBlocks = (N_NODES + WARPS_PER_BLOCK - 1) / WARPS_PER_BLOCK;

    zero_kernel<<<(N_NODES + 256) / 256, 256>>>();
    detect_kernel<<<1, 256>>>((const int*)ei);
    convert_count_kernel<<<(E + 255) / 256, 256>>>(ei, E);
    scan1_kernel<<<SCAN_NBLK, SCAN_BLOCK>>>();
    scan2_kernel<<<1, 64>>>();
    scan3_kernel<<<SCAN_NBLK, SCAN_BLOCK>>>();
    fill_kernel<<<(E + 255) / 256, 256>>>(E);

    // Layer 1: h1 = x @ W1 (50000x128 @ 128x256), proven SIMT SGEMM
    gemm1_kernel<<<dim3(F1 / 128, (N_NODES + 127) / 128), 256>>>(x, W1);
    alpha1_kernel<<<nodeBlocks, 256>>>(att_s1, att_d1);
    agg1_kernel<<<nodeBlocks, 256>>>(b1);

    // Layer 2: h2 = x2 @ W2 (50000x256 @ 256x64), proven SIMT SGEMM
    gemm2_kernel<<<dim3(1, (N_NODES + 127) / 128), 256>>>(W2);
    alpha2_kernel<<<nodeBlocks, 256>>>(att_s2, att_d2);
    agg2_pool_kernel<<<nodeBlocks, 256>>>(b2);

    // Head
    final_kernel<<<1, 64>>>(fc_w, fc_b, out);
}

// round 6
// speedup vs baseline: 1.5418x; 1.1737x over previous
#include <cuda_runtime.h>
#include <cuda_bf16.h>
#include <cuda_fp16.h>
#include <math.h>

// Problem constants (fixed by the reference)
#define N_NODES 50000
#define E_MAX   800000
#define IN_C    128
#define HID     64
#define HEADS   4
#define F1      (HEADS*HID)   // 256
#define OUT_C   64
#define NUM_CLASSES 40

#define SCAN_BLOCK 1024
#define SCAN_NBLK  ((N_NODES + SCAN_BLOCK - 1) / SCAN_BLOCK)   // 49

// ----------------------------------------------------------------------------
// Scratch (device globals: allocation-free per harness rules)
// ----------------------------------------------------------------------------
__device__ __half g_h1h[(size_t)N_NODES * F1];   // layer-1 features (fp16 gather)
__device__ float  g_x2[(size_t)N_NODES * F1];    // layer-1 GAT output (relu'd)
__device__ __half g_h2h[(size_t)N_NODES * OUT_C];// layer-2 features (fp16 gather)
__device__ float  g_as1[N_NODES * HEADS];
__device__ float  g_ad1[N_NODES * HEADS];
__device__ float  g_as2[N_NODES];
__device__ float  g_ad2[N_NODES];
__device__ int    g_counts[N_NODES + 1];
__device__ int    g_rowptr[N_NODES + 1];
__device__ int    g_cursor[N_NODES];
__device__ int    g_src32[E_MAX];
__device__ int    g_dst32[E_MAX];
__device__ int    g_csr_src[E_MAX];
__device__ int    g_blksum[SCAN_NBLK];
__device__ int    g_blkoff[SCAN_NBLK];
__device__ float  g_pooled[OUT_C];
__device__ int    g_is64;

__device__ __forceinline__ float lrelu(float v) { return v > 0.f ? v : 0.2f * v; }

// ----------------------------------------------------------------------------
// 0) zero counts + pooled
// ----------------------------------------------------------------------------
__global__ void zero_kernel() {
    int i = blockIdx.x * blockDim.x + threadIdx.x;
    if (i < N_NODES + 1) g_counts[i] = 0;
    if (i < OUT_C)       g_pooled[i] = 0.f;
}

// ----------------------------------------------------------------------------
// 1) detect whether edge_index is int64 or int32 (JAX x64 ambiguity).
// ----------------------------------------------------------------------------
__global__ void detect_kernel(const int* __restrict__ ei) {
    __shared__ int any;
    if (threadIdx.x == 0) any = 0;
    __syncthreads();
    for (int i = threadIdx.x; i < 4096; i += blockDim.x) {
        if (ei[2 * i + 1] != 0) any = 1;
    }
    __syncthreads();
    if (threadIdx.x == 0) g_is64 = (any == 0) ? 1 : 0;
}

// ----------------------------------------------------------------------------
// 2) convert to int32 + count in-degrees
// ----------------------------------------------------------------------------
__global__ void convert_count_kernel(const void* __restrict__ ei, int E) {
    int e = blockIdx.x * blockDim.x + threadIdx.x;
    if (e >= E) return;
    int s, d;
    if (g_is64) {
        const long long* p = (const long long*)ei;
        s = (int)p[e]; d = (int)p[E + e];
    } else {
        const int* p = (const int*)ei;
        s = p[e]; d = p[E + e];
    }
    g_src32[e] = s;
    g_dst32[e] = d;
    atomicAdd(&g_counts[d], 1);
}

// ----------------------------------------------------------------------------
// 3) parallel exclusive scan of g_counts -> g_rowptr / g_cursor  (PROVEN r4)
// ----------------------------------------------------------------------------
__global__ void __launch_bounds__(SCAN_BLOCK) scan1_kernel() {
    int i = blockIdx.x * SCAN_BLOCK + threadIdx.x;
    int v = (i < N_NODES) ? g_counts[i] : 0;
    __shared__ int sh[32];
    int lane = threadIdx.x & 31, w = threadIdx.x >> 5;
#pragma unroll
    for (int o = 16; o; o >>= 1) v += __shfl_xor_sync(~0u, v, o);
    if (lane == 0) sh[w] = v;
    __syncthreads();
    if (w == 0) {
        int s = sh[lane];
#pragma unroll
        for (int o = 16; o; o >>= 1) s += __shfl_xor_sync(~0u, s, o);
        if (lane == 0) g_blksum[blockIdx.x] = s;
    }
}

__global__ void scan2_kernel() {
    __shared__ int s[64];
    int t = threadIdx.x;
    int v = (t < SCAN_NBLK) ? g_blksum[t] : 0;
    s[t] = v;
    __syncthreads();
#pragma unroll
    for (int o = 1; o < 64; o <<= 1) {
        int u = (t >= o) ? s[t - o] : 0;
        __syncthreads();
        s[t] += u;
        __syncthreads();
    }
    if (t < SCAN_NBLK) g_blkoff[t] = s[t] - v;
    if (t == SCAN_NBLK - 1) g_rowptr[N_NODES] = s[t];
}

__global__ void __launch_bounds__(SCAN_BLOCK) scan3_kernel() {
    int b = blockIdx.x, t = threadIdx.x;
    int i = b * SCAN_BLOCK + t;
    int v = (i < N_NODES) ? g_counts[i] : 0;
    int lane = t & 31, w = t >> 5;
    int inc = v;
#pragma unroll
    for (int o = 1; o < 32; o <<= 1) {
        int u = __shfl_up_sync(~0u, inc, o);
        if (lane >= o) inc += u;
    }
    __shared__ int wsum[32];
    if (lane == 31) wsum[w] = inc;
    __syncthreads();
    if (w == 0) {
        int s = wsum[lane];
#pragma unroll
        for (int o = 1; o < 32; o <<= 1) {
            int u = __shfl_up_sync(~0u, s, o);
            if (lane >= o) s += u;
        }
        wsum[lane] = s;
    }
    __syncthreads();
    int exc = inc - v + (w > 0 ? wsum[w - 1] : 0) + g_blkoff[b];
    if (i < N_NODES) {
        g_rowptr[i] = exc;
        g_cursor[i] = exc;
    }
}

// ----------------------------------------------------------------------------
// 4) fill CSR (src indices grouped by dst)
// ----------------------------------------------------------------------------
__global__ void fill_kernel(int E) {
    int e = blockIdx.x * blockDim.x + threadIdx.x;
    if (e >= E) return;
    int pos = atomicAdd(&g_cursor[g_dst32[e]], 1);
    g_csr_src[pos] = g_src32[e];
}

// ----------------------------------------------------------------------------
// GEMM1 fused: h1 = x @ W1  (50000x128 @ 128x256)
// Proven SIMT mainloop (r1). Epilogue: write fp16 h1h + per-node attention
// logits computed from fp32 accumulators (block covers exactly 2 heads).
// BM=128, BN=128, BK=8, TM=TN=8, 256 threads.
// ----------------------------------------------------------------------------
__global__ void __launch_bounds__(256) gemm1_fused(const float* __restrict__ A,
                                                   const float* __restrict__ B,
                                                   const float* __restrict__ att_s,
                                                   const float* __restrict__ att_d) {
    constexpr int BM = 128, BN = 128, BK = 8, TM = 8, TN = 8;
    constexpr int M = N_NODES, N = F1, K = IN_C;
    __shared__ float As[BK][BM];
    __shared__ float Bs[BK][BN];
    __shared__ float satt_s[BN], satt_d[BN];

    const int tid = threadIdx.x;
    const int block_row = blockIdx.y * BM;
    const int block_col = blockIdx.x * BN;
    const int tx = tid % (BN / TN);   // 0..15
    const int ty = tid / (BN / TN);   // 0..15
    const int lane = tid & 31;

    if (tid < BN) {
        satt_s[tid] = att_s[block_col + tid];
        satt_d[tid] = att_d[block_col + tid];
    }

    float acc[TM][TN];
#pragma unroll
    for (int i = 0; i < TM; i++)
#pragma unroll
        for (int j = 0; j < TN; j++) acc[i][j] = 0.f;

    for (int k0 = 0; k0 < K; k0 += BK) {
        // A tile 128x8: 256 float4 slots
        {
            int r  = tid / (BK / 4);
            int c4 = tid % (BK / 4);
            int gr = block_row + r;
            float4 v = make_float4(0.f, 0.f, 0.f, 0.f);
            if (gr < M) v = *(const float4*)(A + (size_t)gr * K + k0 + c4 * 4);
            As[c4 * 4 + 0][r] = v.x;
            As[c4 * 4 + 1][r] = v.y;
            As[c4 * 4 + 2][r] = v.z;
            As[c4 * 4 + 3][r] = v.w;
        }
        // B tile 8x128: 256 float4 slots
        {
            int r  = tid / (BN / 4);
            int c4 = tid % (BN / 4);
            float4 v = *(const float4*)(B + (size_t)(k0 + r) * N + block_col + c4 * 4);
            *(float4*)(&Bs[r][c4 * 4]) = v;
        }
        __syncthreads();
#pragma unroll
        for (int k = 0; k < BK; k++) {
            float ra[TM], rb[TN];
#pragma unroll
            for (int i = 0; i < TM; i++) ra[i] = As[k][ty * TM + i];
#pragma unroll
            for (int j = 0; j < TN; j++) rb[j] = Bs[k][tx * TN + j];
#pragma unroll
            for (int i = 0; i < TM; i++)
#pragma unroll
                for (int j = 0; j < TN; j++) acc[i][j] += ra[i] * rb[j];
        }
        __syncthreads();
    }

    // Epilogue: fp16 store + alpha logits.
    // lane = (ty&1)*16 + tx. 8-lane groups share (ty, head_local).
    const int head = (block_col >> 6) + (tx >> 3);   // global head id (2 per block)
#pragma unroll
    for (int i = 0; i < TM; i++) {
        int gr = block_row + ty * TM + i;
        bool valid = gr < M;
        __half hbuf[8];
        float as_p = 0.f, ad_p = 0.f;
#pragma unroll
        for (int j = 0; j < TN; j++) {
            float v = acc[i][j];
            hbuf[j] = __float2half(v);
            as_p += v * satt_s[tx * TN + j];
            ad_p += v * satt_d[tx * TN + j];
        }
        if (valid)
            *(uint4*)&g_h1h[(size_t)gr * F1 + block_col + tx * TN] = *(uint4*)hbuf;
#pragma unroll
        for (int o = 1; o < 8; o <<= 1) {
            as_p += __shfl_xor_sync(0xffffffffu, as_p, o);
            ad_p += __shfl_xor_sync(0xffffffffu, ad_p, o);
        }
        if ((lane & 7) == 0 && valid) {
            g_as1[gr * HEADS + head] = as_p;
            g_ad1[gr * HEADS + head] = ad_p;
        }
    }
}

// ----------------------------------------------------------------------------
// GEMM2 fused: h2 = x2 @ W2  (50000x256 @ 256x64), single head.
// BM=128, BN=64, BK=16, TM=8, TN=4, 256 threads.
// ----------------------------------------------------------------------------
__global__ void __launch_bounds__(256) gemm2_fused(const float* __restrict__ B,
                                                   const float* __restrict__ att_s,
                                                   const float* __restrict__ att_d) {
    constexpr int BM = 128, BN = 64, BK = 16, TM = 8, TN = 4;
    constexpr int M = N_NODES, N = OUT_C, K = F1;
    const float* A = g_x2;
    __shared__ float As[BK][BM];
    __shared__ float Bs[BK][BN];
    __shared__ float satt_s[BN], satt_d[BN];

    const int tid = threadIdx.x;
    const int block_row = blockIdx.y * BM;
    const int tx = tid % (BN / TN);   // 0..15
    const int ty = tid / (BN / TN);   // 0..15
    const int lane = tid & 31;

    if (tid < BN) {
        satt_s[tid] = att_s[tid];
        satt_d[tid] = att_d[tid];
    }

    float acc[TM][TN];
#pragma unroll
    for (int i = 0; i < TM; i++)
#pragma unroll
        for (int j = 0; j < TN; j++) acc[i][j] = 0.f;

    for (int k0 = 0; k0 < K; k0 += BK) {
        // A tile 128x16: 512 float4 slots -> 2 per thread
#pragma unroll
        for (int it = 0; it < 2; it++) {
            int idx = tid + it * 256;
            int r  = idx / (BK / 4);
            int c4 = idx % (BK / 4);
            int gr = block_row + r;
            float4 v = make_float4(0.f, 0.f, 0.f, 0.f);
            if (gr < M) v = *(const float4*)(A + (size_t)gr * K + k0 + c4 * 4);
            As[c4 * 4 + 0][r] = v.x;
            As[c4 * 4 + 1][r] = v.y;
            As[c4 * 4 + 2][r] = v.z;
            As[c4 * 4 + 3][r] = v.w;
        }
        // B tile 16x64: 256 float4 slots
        {
            int r  = tid / (BN / 4);
            int c4 = tid % (BN / 4);
            float4 v = *(const float4*)(B + (size_t)(k0 + r) * N + c4 * 4);
            *(float4*)(&Bs[r][c4 * 4]) = v;
        }
        __syncthreads();
#pragma unroll
        for (int k = 0; k < BK; k++) {
            float ra[TM], rb[TN];
#pragma unroll
            for (int i = 0; i < TM; i++) ra[i] = As[k][ty * TM + i];
#pragma unroll
            for (int j = 0; j < TN; j++) rb[j] = Bs[k][tx * TN + j];
#pragma unroll
            for (int i = 0; i < TM; i++)
#pragma unroll
                for (int j = 0; j < TN; j++) acc[i][j] += ra[i] * rb[j];
        }
        __syncthreads();
    }

    // Epilogue: fp16 store + single-head alpha (reduce across 16 lanes).
#pragma unroll
    for (int i = 0; i < TM; i++) {
        int gr = block_row + ty * TM + i;
        bool valid = gr < M;
        __half hbuf[4];
        float as_p = 0.f, ad_p = 0.f;
#pragma unroll
        for (int j = 0; j < TN; j++) {
            float v = acc[i][j];
            hbuf[j] = __float2half(v);
            as_p += v * satt_s[tx * TN + j];
            ad_p += v * satt_d[tx * TN + j];
        }
        if (valid)
            *(uint2*)&g_h2h[(size_t)gr * OUT_C + tx * TN] = *(uint2*)hbuf;
#pragma unroll
        for (int o = 1; o < 16; o <<= 1) {
            as_p += __shfl_xor_sync(0xffffffffu, as_p, o);
            ad_p += __shfl_xor_sync(0xffffffffu, ad_p, o);
        }
        if ((lane & 15) == 0 && valid) {
            g_as2[gr] = as_p;
            g_ad2[gr] = ad_p;
        }
    }
}

// ----------------------------------------------------------------------------
// Layer-1 aggregation: warp per dst node, single-pass softmax, fp16 gathers,
// fp32 accumulation. Fuses +b1 and relu. (PROVEN r5)
// ----------------------------------------------------------------------------
__global__ void agg1_kernel(const float* __restrict__ b1) {
    int t = threadIdx.x;
    int warp = (blockIdx.x * blockDim.x + t) >> 5;
    if (warp >= N_NODES) return;
    int lane = t & 31;
    int d = warp;
    int head = lane >> 3;

    float ad = g_ad1[d * HEADS + head];
    int beg = g_rowptr[d], end = g_rowptr[d + 1];

    float denom = 1e-16f;
    float acc[8] = {0.f, 0.f, 0.f, 0.f, 0.f, 0.f, 0.f, 0.f};
    for (int i = beg; i < end; i++) {
        int s = g_csr_src[i];
        float w = __expf(lrelu(g_as1[s * HEADS + head] + ad));
        denom += w;
        uint4 u = *(const uint4*)&g_h1h[(size_t)s * F1 + lane * 8];
        float2 f0 = __half22float2(*reinterpret_cast<__half2*>(&u.x));
        float2 f1 = __half22float2(*reinterpret_cast<__half2*>(&u.y));
        float2 f2 = __half22float2(*reinterpret_cast<__half2*>(&u.z));
        float2 f3 = __half22float2(*reinterpret_cast<__half2*>(&u.w));
        acc[0] += w * f0.x; acc[1] += w * f0.y;
        acc[2] += w * f1.x; acc[3] += w * f1.y;
        acc[4] += w * f2.x; acc[5] += w * f2.y;
        acc[6] += w * f3.x; acc[7] += w * f3.y;
    }
    {   // self loop
        float w = __expf(lrelu(g_as1[d * HEADS + head] + ad));
        denom += w;
        uint4 u = *(const uint4*)&g_h1h[(size_t)d * F1 + lane * 8];
        float2 f0 = __half22float2(*reinterpret_cast<__half2*>(&u.x));
        float2 f1 = __half22float2(*reinterpret_cast<__half2*>(&u.y));
        float2 f2 = __half22float2(*reinterpret_cast<__half2*>(&u.z));
        float2 f3 = __half22float2(*reinterpret_cast<__half2*>(&u.w));
        acc[0] += w * f0.x; acc[1] += w * f0.y;
        acc[2] += w * f1.x; acc[3] += w * f1.y;
        acc[4] += w * f2.x; acc[5] += w * f2.y;
        acc[6] += w * f3.x; acc[7] += w * f3.y;
    }
    float inv = 1.f / denom;
    int cb = lane * 8;
    float4 o0, o1;
    o0.x = fmaxf(acc[0] * inv + b1[cb + 0], 0.f);
    o0.y = fmaxf(acc[1] * inv + b1[cb + 1], 0.f);
    o0.z = fmaxf(acc[2] * inv + b1[cb + 2], 0.f);
    o0.w = fmaxf(acc[3] * inv + b1[cb + 3], 0.f);
    o1.x = fmaxf(acc[4] * inv + b1[cb + 4], 0.f);
    o1.y = fmaxf(acc[5] * inv + b1[cb + 5], 0.f);
    o1.z = fmaxf(acc[6] * inv + b1[cb + 6], 0.f);
    o1.w = fmaxf(acc[7] * inv + b1[cb + 7], 0.f);
    *(float4*)&g_x2[(size_t)d * F1 + cb]     = o0;
    *(float4*)&g_x2[(size_t)d * F1 + cb + 4] = o1;
}

// ----------------------------------------------------------------------------
// Layer-2 aggregation (heads=1) + bias + relu + global mean-pool accumulation.
// ----------------------------------------------------------------------------
__global__ void agg2_pool_kernel(const float* __restrict__ b2) {
    __shared__ float sp[OUT_C];
    int t = threadIdx.x;
    if (t < OUT_C) sp[t] = 0.f;
    __syncthreads();

    int warp = (blockIdx.x * blockDim.x + t) >> 5;
    int lane = t & 31;
    if (warp < N_NODES) {
        int d = warp;
        float ad = g_ad2[d];
        int beg = g_rowptr[d], end = g_rowptr[d + 1];

        float denom = 1e-16f;
        float a0 = 0.f, a1 = 0.f;
        for (int i = beg; i < end; i++) {
            int s = g_csr_src[i];
            float w = __expf(lrelu(g_as2[s] + ad));
            denom += w;
            a0 += w * __half2float(g_h2h[(size_t)s * OUT_C + lane]);
            a1 += w * __half2float(g_h2h[(size_t)s * OUT_C + 32 + lane]);
        }
        {
            float w = __expf(lrelu(g_as2[d] + ad));
            denom += w;
            a0 += w * __half2float(g_h2h[(size_t)d * OUT_C + lane]);
            a1 += w * __half2float(g_h2h[(size_t)d * OUT_C + 32 + lane]);
        }
        float inv = 1.f / denom;
        float v0 = fmaxf(a0 * inv + b2[lane], 0.f);
        float v1 = fmaxf(a1 * inv + b2[32 + lane], 0.f);
        atomicAdd(&sp[lane], v0);
        atomicAdd(&sp[32 + lane], v1);
    }
    __syncthreads();
    if (t < OUT_C) atomicAdd(&g_pooled[t], sp[t]);
}

// ----------------------------------------------------------------------------
// Final: mean-pool scale, FC to 40 classes, log_softmax
// ----------------------------------------------------------------------------
__global__ void final_kernel(const float* __restrict__ fc_w,
                             const float* __restrict__ fc_b,
                             float* __restrict__ out) {
    __shared__ float p[OUT_C];
    __shared__ float lg[NUM_CLASSES];
    __shared__ float lse_sh;
    int t = threadIdx.x;  // 64 threads
    p[t] = g_pooled[t] * (1.0f / (float)N_NODES);
    __syncthreads();
    if (t < NUM_CLASSES) {
        float s = fc_b[t];
#pragma unroll
        for (int c = 0; c < OUT_C; c++) s += p[c] * fc_w[c * NUM_CLASSES + t];
        lg[t] = s;
    }
    __syncthreads();
    if (t == 0) {
        float mx = lg[0];
        for (int j = 1; j < NUM_CLASSES; j++) mx = fmaxf(mx, lg[j]);
        float se = 0.f;
        for (int j = 0; j < NUM_CLASSES; j++) se += expf(lg[j] - mx);
        lse_sh = mx + logf(se);
    }
    __syncthreads();
    if (t < NUM_CLASSES) out[t] = lg[t] - lse_sh;
}

// ----------------------------------------------------------------------------
// launch
// ----------------------------------------------------------------------------
extern "C" void kernel_launch(void* const* d_in, const int* in_sizes, int n_in,
                              void* d_out, int out_size) {
    const float* x      = (const float*)d_in[0];
    const void*  ei     = d_in[1];
    const float* W1     = (const float*)d_in[2];
    const float* att_s1 = (const float*)d_in[3];
    const float* att_d1 = (const float*)d_in[4];
    const float* b1     = (const float*)d_in[5];
    const float* W2     = (const float*)d_in[6];
    const float* att_s2 = (const float*)d_in[7];
    const float* att_d2 = (const float*)d_in[8];
    const float* b2     = (const float*)d_in[9];
    const float* fc_w   = (const float*)d_in[10];
    const float* fc_b   = (const float*)d_in[11];
    float* out = (float*)d_out;

    int E = in_sizes[1] / 2;
    if (E > E_MAX) E = E_MAX;

    const int WARPS_PER_BLOCK = 8;
    const int nodeBlocks = (N_NODES + WARPS_PER_BLOCK - 1) / WARPS_PER_BLOCK;
    const int mBlocks = (N_NODES + 127) / 128;

    zero_kernel<<<(N_NODES + 256) / 256, 256>>>();
    detect_kernel<<<1, 256>>>((const int*)ei);
    convert_count_kernel<<<(E + 255) / 256, 256>>>(ei, E);
    scan1_kernel<<<SCAN_NBLK, SCAN_BLOCK>>>();
    scan2_kernel<<<1, 64>>>();
    scan3_kernel<<<SCAN_NBLK, SCAN_BLOCK>>>();
    fill_kernel<<<(E + 255) / 256, 256>>>(E);

    // Layer 1: fused GEMM + fp16 convert + alpha logits
    gemm1_fused<<<dim3(F1 / 128, mBlocks), 256>>>(x, W1, att_s1, att_d1);
    agg1_kernel<<<nodeBlocks, 256>>>(b1);

    // Layer 2: fused GEMM + fp16 convert + alpha logits
    gemm2_fused<<<dim3(1, mBlocks), 256>>>(W2, att_s2, att_d2);
    agg2_pool_kernel<<<nodeBlocks, 256>>>(b2);

    // Head
    final_kernel<<<1, 64>>>(fc_w, fc_b, out);
}

// round 7
// speedup vs baseline: 1.9649x; 1.2744x over previous
#include <cuda_runtime.h>
#include <cuda_bf16.h>
#include <cuda_fp16.h>
#include <math.h>

// Problem constants (fixed by the reference)
#define N_NODES 50000
#define E_MAX   800000
#define IN_C    128
#define HID     64
#define HEADS   4
#define F1      (HEADS*HID)   // 256
#define OUT_C   64
#define NUM_CLASSES 40

#define SCAN_BLOCK 1024
#define SCAN_NBLK  ((N_NODES + SCAN_BLOCK - 1) / SCAN_BLOCK)   // 49

// ----------------------------------------------------------------------------
// Scratch (device globals: allocation-free per harness rules)
// ----------------------------------------------------------------------------
__device__ __half g_h1h[(size_t)N_NODES * F1];   // layer-1 features (fp16 gather)
__device__ float  g_x2[(size_t)N_NODES * F1];    // layer-1 GAT output (relu'd)
__device__ __half g_h2h[(size_t)N_NODES * OUT_C];// layer-2 features (fp16 gather)
__device__ float  g_as1[N_NODES * HEADS];
__device__ float  g_ad1[N_NODES * HEADS];
__device__ float  g_as2[N_NODES];
__device__ float  g_ad2[N_NODES];
__device__ int    g_counts[N_NODES + 1];
__device__ int    g_rowptr[N_NODES + 1];
__device__ int    g_cursor[N_NODES];
__device__ int    g_src32[E_MAX];
__device__ int    g_dst32[E_MAX];
__device__ int    g_csr_src[E_MAX];
__device__ int    g_blksum[SCAN_NBLK];
__device__ int    g_blkoff[SCAN_NBLK];
__device__ float  g_pooled[OUT_C];
__device__ int    g_is64;

__device__ __forceinline__ float lrelu(float v) { return v > 0.f ? v : 0.2f * v; }

__device__ __forceinline__ void split_h(float v, __half& hi, __half& lo) {
    hi = __float2half(v);
    lo = __float2half(v - __half2float(hi));
}

// m16n8k16 fp16 MMA, fp32 accumulate
__device__ __forceinline__ void mma_f16(float* c, const unsigned* a, const unsigned* b) {
    asm volatile(
        "mma.sync.aligned.m16n8k16.row.col.f32.f16.f16.f32 "
        "{%0,%1,%2,%3}, {%4,%5,%6,%7}, {%8,%9}, {%0,%1,%2,%3};\n"
        : "+f"(c[0]), "+f"(c[1]), "+f"(c[2]), "+f"(c[3])
        : "r"(a[0]), "r"(a[1]), "r"(a[2]), "r"(a[3]), "r"(b[0]), "r"(b[1]));
}

// ----------------------------------------------------------------------------
// 0) zero counts + pooled
// ----------------------------------------------------------------------------
__global__ void zero_kernel() {
    int i = blockIdx.x * blockDim.x + threadIdx.x;
    if (i < N_NODES + 1) g_counts[i] = 0;
    if (i < OUT_C)       g_pooled[i] = 0.f;
}

// ----------------------------------------------------------------------------
// 1) detect whether edge_index is int64 or int32 (JAX x64 ambiguity).
// ----------------------------------------------------------------------------
__global__ void detect_kernel(const int* __restrict__ ei) {
    __shared__ int any;
    if (threadIdx.x == 0) any = 0;
    __syncthreads();
    for (int i = threadIdx.x; i < 4096; i += blockDim.x) {
        if (ei[2 * i + 1] != 0) any = 1;
    }
    __syncthreads();
    if (threadIdx.x == 0) g_is64 = (any == 0) ? 1 : 0;
}

// ----------------------------------------------------------------------------
// 2) convert to int32 + count in-degrees
// ----------------------------------------------------------------------------
__global__ void convert_count_kernel(const void* __restrict__ ei, int E) {
    int e = blockIdx.x * blockDim.x + threadIdx.x;
    if (e >= E) return;
    int s, d;
    if (g_is64) {
        const long long* p = (const long long*)ei;
        s = (int)p[e]; d = (int)p[E + e];
    } else {
        const int* p = (const int*)ei;
        s = p[e]; d = p[E + e];
    }
    g_src32[e] = s;
    g_dst32[e] = d;
    atomicAdd(&g_counts[d], 1);
}

// ----------------------------------------------------------------------------
// 3) parallel exclusive scan of g_counts -> g_rowptr / g_cursor  (PROVEN r4)
// ----------------------------------------------------------------------------
__global__ void __launch_bounds__(SCAN_BLOCK) scan1_kernel() {
    int i = blockIdx.x * SCAN_BLOCK + threadIdx.x;
    int v = (i < N_NODES) ? g_counts[i] : 0;
    __shared__ int sh[32];
    int lane = threadIdx.x & 31, w = threadIdx.x >> 5;
#pragma unroll
    for (int o = 16; o; o >>= 1) v += __shfl_xor_sync(~0u, v, o);
    if (lane == 0) sh[w] = v;
    __syncthreads();
    if (w == 0) {
        int s = sh[lane];
#pragma unroll
        for (int o = 16; o; o >>= 1) s += __shfl_xor_sync(~0u, s, o);
        if (lane == 0) g_blksum[blockIdx.x] = s;
    }
}

__global__ void scan2_kernel() {
    __shared__ int s[64];
    int t = threadIdx.x;
    int v = (t < SCAN_NBLK) ? g_blksum[t] : 0;
    s[t] = v;
    __syncthreads();
#pragma unroll
    for (int o = 1; o < 64; o <<= 1) {
        int u = (t >= o) ? s[t - o] : 0;
        __syncthreads();
        s[t] += u;
        __syncthreads();
    }
    if (t < SCAN_NBLK) g_blkoff[t] = s[t] - v;
    if (t == SCAN_NBLK - 1) g_rowptr[N_NODES] = s[t];
}

__global__ void __launch_bounds__(SCAN_BLOCK) scan3_kernel() {
    int b = blockIdx.x, t = threadIdx.x;
    int i = b * SCAN_BLOCK + t;
    int v = (i < N_NODES) ? g_counts[i] : 0;
    int lane = t & 31, w = t >> 5;
    int inc = v;
#pragma unroll
    for (int o = 1; o < 32; o <<= 1) {
        int u = __shfl_up_sync(~0u, inc, o);
        if (lane >= o) inc += u;
    }
    __shared__ int wsum[32];
    if (lane == 31) wsum[w] = inc;
    __syncthreads();
    if (w == 0) {
        int s = wsum[lane];
#pragma unroll
        for (int o = 1; o < 32; o <<= 1) {
            int u = __shfl_up_sync(~0u, s, o);
            if (lane >= o) s += u;
        }
        wsum[lane] = s;
    }
    __syncthreads();
    int exc = inc - v + (w > 0 ? wsum[w - 1] : 0) + g_blkoff[b];
    if (i < N_NODES) {
        g_rowptr[i] = exc;
        g_cursor[i] = exc;
    }
}

// ----------------------------------------------------------------------------
// 4) fill CSR (src indices grouped by dst)
// ----------------------------------------------------------------------------
__global__ void fill_kernel(int E) {
    int e = blockIdx.x * blockDim.x + threadIdx.x;
    if (e >= E) return;
    int pos = atomicAdd(&g_cursor[g_dst32[e]], 1);
    g_csr_src[pos] = g_src32[e];
}

// ----------------------------------------------------------------------------
// GEMM1 fused (3xFP16 HMMA): h1 = x @ W1  (50000x128 @ 128x256)
// BM=128, BN=128, BK=32. 8 warps: 4 along M x 2 along N; warp tile 32x64
// (one head per warp). Epilogue: fp16 store + alpha logits from fp32 acc.
// ----------------------------------------------------------------------------
__global__ void __launch_bounds__(256) gemm1_fused(const float* __restrict__ A,
                                                   const float* __restrict__ B,
                                                   const float* __restrict__ att_s,
                                                   const float* __restrict__ att_d) {
    constexpr int M = N_NODES, N = F1, K = IN_C;
    constexpr int BM = 128, BN = 128, BK = 32;
    constexpr int SKA = BK + 8;           // padded stride (halves)
    __shared__ __half Ah[BM][SKA], Al[BM][SKA];
    __shared__ __half BhT[BN][SKA], BlT[BN][SKA];   // transposed [n][k]
    __shared__ float satt_s[BN], satt_d[BN];

    const int tid = threadIdx.x;
    const int lane = tid & 31, warp = tid >> 5;
    const int g = lane >> 2, t = lane & 3;
    const int warp_m = warp & 3;      // 0..3
    const int warp_n = warp >> 2;     // 0..1
    const int block_row = blockIdx.y * BM;
    const int block_col = blockIdx.x * BN;

    if (tid < BN) {
        satt_s[tid] = att_s[block_col + tid];
        satt_d[tid] = att_d[block_col + tid];
    }

    float acc[2][8][4];
#pragma unroll
    for (int mt = 0; mt < 2; mt++)
#pragma unroll
        for (int nt = 0; nt < 8; nt++)
#pragma unroll
            for (int q = 0; q < 4; q++) acc[mt][nt][q] = 0.f;

    for (int k0 = 0; k0 < K; k0 += BK) {
        // A tile 128x32 fp32 -> hi/lo halves. 256 thr x 4 float4.
#pragma unroll
        for (int it = 0; it < 4; it++) {
            int idx = tid + it * 256;
            int r  = idx >> 3;
            int c4 = idx & 7;
            int gr = block_row + r;
            float4 v = make_float4(0.f, 0.f, 0.f, 0.f);
            if (gr < M) v = *(const float4*)(A + (size_t)gr * K + k0 + c4 * 4);
            __half h0, l0, h1, l1, h2, l2, h3, l3;
            split_h(v.x, h0, l0); split_h(v.y, h1, l1);
            split_h(v.z, h2, l2); split_h(v.w, h3, l3);
            int c = c4 * 4;
            Ah[r][c + 0] = h0; Ah[r][c + 1] = h1; Ah[r][c + 2] = h2; Ah[r][c + 3] = h3;
            Al[r][c + 0] = l0; Al[r][c + 1] = l1; Al[r][c + 2] = l2; Al[r][c + 3] = l3;
        }
        // B tile 32x128 fp32 -> transposed hi/lo halves. n = tid%128, two k halves.
        {
            int n  = tid & 127;
            int kb = (tid >> 7) * 16;     // 0 or 16
#pragma unroll
            for (int i = 0; i < 16; i++) {
                int k = kb + i;
                float v = B[(size_t)(k0 + k) * N + block_col + n];
                __half h, l; split_h(v, h, l);
                BhT[n][k] = h; BlT[n][k] = l;
            }
        }
        __syncthreads();
#pragma unroll
        for (int ks = 0; ks < 2; ks++) {
            const int kk = ks * 16;
            unsigned ah[2][4], al[2][4];
#pragma unroll
            for (int mt = 0; mt < 2; mt++) {
                int r0 = warp_m * 32 + mt * 16 + g;
                ah[mt][0] = *(const unsigned*)&Ah[r0][kk + 2 * t];
                ah[mt][1] = *(const unsigned*)&Ah[r0 + 8][kk + 2 * t];
                ah[mt][2] = *(const unsigned*)&Ah[r0][kk + 2 * t + 8];
                ah[mt][3] = *(const unsigned*)&Ah[r0 + 8][kk + 2 * t + 8];
                al[mt][0] = *(const unsigned*)&Al[r0][kk + 2 * t];
                al[mt][1] = *(const unsigned*)&Al[r0 + 8][kk + 2 * t];
                al[mt][2] = *(const unsigned*)&Al[r0][kk + 2 * t + 8];
                al[mt][3] = *(const unsigned*)&Al[r0 + 8][kk + 2 * t + 8];
            }
#pragma unroll
            for (int nt = 0; nt < 8; nt++) {
                int n0 = warp_n * 64 + nt * 8 + g;
                unsigned bh[2], bl[2];
                bh[0] = *(const unsigned*)&BhT[n0][kk + 2 * t];
                bh[1] = *(const unsigned*)&BhT[n0][kk + 2 * t + 8];
                bl[0] = *(const unsigned*)&BlT[n0][kk + 2 * t];
                bl[1] = *(const unsigned*)&BlT[n0][kk + 2 * t + 8];
#pragma unroll
                for (int mt = 0; mt < 2; mt++) {
                    mma_f16(acc[mt][nt], ah[mt], bl);   // cross terms first
                    mma_f16(acc[mt][nt], al[mt], bh);
                    mma_f16(acc[mt][nt], ah[mt], bh);
                }
            }
        }
        __syncthreads();
    }

    // Epilogue: fp16 store + alpha logits. Quad (4 lanes) shares each row.
    const int head = blockIdx.x * 2 + warp_n;
#pragma unroll
    for (int mt = 0; mt < 2; mt++) {
#pragma unroll
        for (int rr = 0; rr < 2; rr++) {
            int grow = block_row + warp_m * 32 + mt * 16 + g + rr * 8;
            bool valid = grow < M;
            float as_p = 0.f, ad_p = 0.f;
#pragma unroll
            for (int nt = 0; nt < 8; nt++) {
                float v0 = acc[mt][nt][rr * 2 + 0];
                float v1 = acc[mt][nt][rr * 2 + 1];
                int col = warp_n * 64 + nt * 8 + 2 * t;
                as_p += v0 * satt_s[col] + v1 * satt_s[col + 1];
                ad_p += v0 * satt_d[col] + v1 * satt_d[col + 1];
                if (valid) {
                    __half2 hv = __floats2half2_rn(v0, v1);
                    *(__half2*)&g_h1h[(size_t)grow * F1 + block_col + col] = hv;
                }
            }
            as_p += __shfl_xor_sync(0xffffffffu, as_p, 1);
            as_p += __shfl_xor_sync(0xffffffffu, as_p, 2);
            ad_p += __shfl_xor_sync(0xffffffffu, ad_p, 1);
            ad_p += __shfl_xor_sync(0xffffffffu, ad_p, 2);
            if (t == 0 && valid) {
                g_as1[grow * HEADS + head] = as_p;
                g_ad1[grow * HEADS + head] = ad_p;
            }
        }
    }
}

// ----------------------------------------------------------------------------
// GEMM2 fused (3xFP16 HMMA): h2 = x2 @ W2  (50000x256 @ 256x64), single head.
// BM=128, BN=64, BK=32. 4 warps along M; warp tile 32x64.
// ----------------------------------------------------------------------------
__global__ void __launch_bounds__(128) gemm2_fused(const float* __restrict__ B,
                                                   const float* __restrict__ att_s,
                                                   const float* __restrict__ att_d) {
    constexpr int M = N_NODES, N = OUT_C, K = F1;
    constexpr int BM = 128, BN = 64, BK = 32;
    constexpr int SKA = BK + 8;
    const float* A = g_x2;
    __shared__ __half Ah[BM][SKA], Al[BM][SKA];
    __shared__ __half BhT[BN][SKA], BlT[BN][SKA];
    __shared__ float satt_s[BN], satt_d[BN];

    const int tid = threadIdx.x;
    const int lane = tid & 31, warp = tid >> 5;   // 4 warps
    const int g = lane >> 2, t = lane & 3;
    const int block_row = blockIdx.y * BM;

    if (tid < BN) {
        satt_s[tid] = att_s[tid];
        satt_d[tid] = att_d[tid];
    }

    float acc[2][8][4];
#pragma unroll
    for (int mt = 0; mt < 2; mt++)
#pragma unroll
        for (int nt = 0; nt < 8; nt++)
#pragma unroll
            for (int q = 0; q < 4; q++) acc[mt][nt][q] = 0.f;

    for (int k0 = 0; k0 < K; k0 += BK) {
        // A tile 128x32 fp32: 128 thr x 8 float4
#pragma unroll
        for (int it = 0; it < 8; it++) {
            int idx = tid + it * 128;
            int r  = idx >> 3;
            int c4 = idx & 7;
            int gr = block_row + r;
            float4 v = make_float4(0.f, 0.f, 0.f, 0.f);
            if (gr < M) v = *(const float4*)(A + (size_t)gr * K + k0 + c4 * 4);
            __half h0, l0, h1, l1, h2, l2, h3, l3;
            split_h(v.x, h0, l0); split_h(v.y, h1, l1);
            split_h(v.z, h2, l2); split_h(v.w, h3, l3);
            int c = c4 * 4;
            Ah[r][c + 0] = h0; Ah[r][c + 1] = h1; Ah[r][c + 2] = h2; Ah[r][c + 3] = h3;
            Al[r][c + 0] = l0; Al[r][c + 1] = l1; Al[r][c + 2] = l2; Al[r][c + 3] = l3;
        }
        // B tile 32x64 fp32 -> transposed. n = tid%64, two k halves.
        {
            int n  = tid & 63;
            int kb = (tid >> 6) * 16;
#pragma unroll
            for (int i = 0; i < 16; i++) {
                int k = kb + i;
                float v = B[(size_t)(k0 + k) * N + n];
                __half h, l; split_h(v, h, l);
                BhT[n][k] = h; BlT[n][k] = l;
            }
        }
        __syncthreads();
#pragma unroll
        for (int ks = 0; ks < 2; ks++) {
            const int kk = ks * 16;
            unsigned ah[2][4], al[2][4];
#pragma unroll
            for (int mt = 0; mt < 2; mt++) {
                int r0 = warp * 32 + mt * 16 + g;
                ah[mt][0] = *(const unsigned*)&Ah[r0][kk + 2 * t];
                ah[mt][1] = *(const unsigned*)&Ah[r0 + 8][kk + 2 * t];
                ah[mt][2] = *(const unsigned*)&Ah[r0][kk + 2 * t + 8];
                ah[mt][3] = *(const unsigned*)&Ah[r0 + 8][kk + 2 * t + 8];
                al[mt][0] = *(const unsigned*)&Al[r0][kk + 2 * t];
                al[mt][1] = *(const unsigned*)&Al[r0 + 8][kk + 2 * t];
                al[mt][2] = *(const unsigned*)&Al[r0][kk + 2 * t + 8];
                al[mt][3] = *(const unsigned*)&Al[r0 + 8][kk + 2 * t + 8];
            }
#pragma unroll
            for (int nt = 0; nt < 8; nt++) {
                int n0 = nt * 8 + g;
                unsigned bh[2], bl[2];
                bh[0] = *(const unsigned*)&BhT[n0][kk + 2 * t];
                bh[1] = *(const unsigned*)&BhT[n0][kk + 2 * t + 8];
                bl[0] = *(const unsigned*)&BlT[n0][kk + 2 * t];
                bl[1] = *(const unsigned*)&BlT[n0][kk + 2 * t + 8];
#pragma unroll
                for (int mt = 0; mt < 2; mt++) {
                    mma_f16(acc[mt][nt], ah[mt], bl);
                    mma_f16(acc[mt][nt], al[mt], bh);
                    mma_f16(acc[mt][nt], ah[mt], bh);
                }
            }
        }
        __syncthreads();
    }

    // Epilogue: fp16 store + single-head alpha logits
#pragma unroll
    for (int mt = 0; mt < 2; mt++) {
#pragma unroll
        for (int rr = 0; rr < 2; rr++) {
            int grow = block_row + warp * 32 + mt * 16 + g + rr * 8;
            bool valid = grow < M;
            float as_p = 0.f, ad_p = 0.f;
#pragma unroll
            for (int nt = 0; nt < 8; nt++) {
                float v0 = acc[mt][nt][rr * 2 + 0];
                float v1 = acc[mt][nt][rr * 2 + 1];
                int col = nt * 8 + 2 * t;
                as_p += v0 * satt_s[col] + v1 * satt_s[col + 1];
                ad_p += v0 * satt_d[col] + v1 * satt_d[col + 1];
                if (valid) {
                    __half2 hv = __floats2half2_rn(v0, v1);
                    *(__half2*)&g_h2h[(size_t)grow * OUT_C + col] = hv;
                }
            }
            as_p += __shfl_xor_sync(0xffffffffu, as_p, 1);
            as_p += __shfl_xor_sync(0xffffffffu, as_p, 2);
            ad_p += __shfl_xor_sync(0xffffffffu, ad_p, 1);
            ad_p += __shfl_xor_sync(0xffffffffu, ad_p, 2);
            if (t == 0 && valid) {
                g_as2[grow] = as_p;
                g_ad2[grow] = ad_p;
            }
        }
    }
}

// ----------------------------------------------------------------------------
// Layer-1 aggregation: warp per dst node, single-pass softmax, fp16 gathers,
// fp32 accumulation. Fuses +b1 and relu. (PROVEN r5/r6)
// ----------------------------------------------------------------------------
__global__ void agg1_kernel(const float* __restrict__ b1) {
    int t = threadIdx.x;
    int warp = (blockIdx.x * blockDim.x + t) >> 5;
    if (warp >= N_NODES) return;
    int lane = t & 31;
    int d = warp;
    int head = lane >> 3;

    float ad = g_ad1[d * HEADS + head];
    int beg = g_rowptr[d], end = g_rowptr[d + 1];

    float denom = 1e-16f;
    float acc[8] = {0.f, 0.f, 0.f, 0.f, 0.f, 0.f, 0.f, 0.f};
    for (int i = beg; i < end; i++) {
        int s = g_csr_src[i];
        float w = __expf(lrelu(g_as1[s * HEADS + head] + ad));
        denom += w;
        uint4 u = *(const uint4*)&g_h1h[(size_t)s * F1 + lane * 8];
        float2 f0 = __half22float2(*reinterpret_cast<__half2*>(&u.x));
        float2 f1 = __half22float2(*reinterpret_cast<__half2*>(&u.y));
        float2 f2 = __half22float2(*reinterpret_cast<__half2*>(&u.z));
        float2 f3 = __half22float2(*reinterpret_cast<__half2*>(&u.w));
        acc[0] += w * f0.x; acc[1] += w * f0.y;
        acc[2] += w * f1.x; acc[3] += w * f1.y;
        acc[4] += w * f2.x; acc[5] += w * f2.y;
        acc[6] += w * f3.x; acc[7] += w * f3.y;
    }
    {   // self loop
        float w = __expf(lrelu(g_as1[d * HEADS + head] + ad));
        denom += w;
        uint4 u = *(const uint4*)&g_h1h[(size_t)d * F1 + lane * 8];
        float2 f0 = __half22float2(*reinterpret_cast<__half2*>(&u.x));
        float2 f1 = __half22float2(*reinterpret_cast<__half2*>(&u.y));
        float2 f2 = __half22float2(*reinterpret_cast<__half2*>(&u.z));
        float2 f3 = __half22float2(*reinterpret_cast<__half2*>(&u.w));
        acc[0] += w * f0.x; acc[1] += w * f0.y;
        acc[2] += w * f1.x; acc[3] += w * f1.y;
        acc[4] += w * f2.x; acc[5] += w * f2.y;
        acc[6] += w * f3.x; acc[7] += w * f3.y;
    }
    float inv = 1.f / denom;
    int cb = lane * 8;
    float4 o0, o1;
    o0.x = fmaxf(acc[0] * inv + b1[cb + 0], 0.f);
    o0.y = fmaxf(acc[1] * inv + b1[cb + 1], 0.f);
    o0.z = fmaxf(acc[2] * inv + b1[cb + 2], 0.f);
    o0.w = fmaxf(acc[3] * inv + b1[cb + 3], 0.f);
    o1.x = fmaxf(acc[4] * inv + b1[cb + 4], 0.f);
    o1.y = fmaxf(acc[5] * inv + b1[cb + 5], 0.f);
    o1.z = fmaxf(acc[6] * inv + b1[cb + 6], 0.f);
    o1.w = fmaxf(acc[7] * inv + b1[cb + 7], 0.f);
    *(float4*)&g_x2[(size_t)d * F1 + cb]     = o0;
    *(float4*)&g_x2[(size_t)d * F1 + cb + 4] = o1;
}

// ----------------------------------------------------------------------------
// Layer-2 aggregation (heads=1) + bias + relu + global mean-pool accumulation.
// ----------------------------------------------------------------------------
__global__ void agg2_pool_kernel(const float* __restrict__ b2) {
    __shared__ float sp[OUT_C];
    int t = threadIdx.x;
    if (t < OUT_C) sp[t] = 0.f;
    __syncthreads();

    int warp = (blockIdx.x * blockDim.x + t) >> 5;
    int lane = t & 31;
    if (warp < N_NODES) {
        int d = warp;
        float ad = g_ad2[d];
        int beg = g_rowptr[d], end = g_rowptr[d + 1];

        float denom = 1e-16f;
        float a0 = 0.f, a1 = 0.f;
        for (int i = beg; i < end; i++) {
            int s = g_csr_src[i];
            float w = __expf(lrelu(g_as2[s] + ad));
            denom += w;
            a0 += w * __half2float(g_h2h[(size_t)s * OUT_C + lane]);
            a1 += w * __half2float(g_h2h[(size_t)s * OUT_C + 32 + lane]);
        }
        {
            float w = __expf(lrelu(g_as2[d] + ad));
            denom += w;
            a0 += w * __half2float(g_h2h[(size_t)d * OUT_C + lane]);
            a1 += w * __half2float(g_h2h[(size_t)d * OUT_C + 32 + lane]);
        }
        float inv = 1.f / denom;
        float v0 = fmaxf(a0 * inv + b2[lane], 0.f);
        float v1 = fmaxf(a1 * inv + b2[32 + lane], 0.f);
        atomicAdd(&sp[lane], v0);
        atomicAdd(&sp[32 + lane], v1);
    }
    __syncthreads();
    if (t < OUT_C) atomicAdd(&g_pooled[t], sp[t]);
}

// ----------------------------------------------------------------------------
// Final: mean-pool scale, FC to 40 classes, log_softmax
// ----------------------------------------------------------------------------
__global__ void final_kernel(const float* __restrict__ fc_w,
                             const float* __restrict__ fc_b,
                             float* __restrict__ out) {
    __shared__ float p[OUT_C];
    __shared__ float lg[NUM_CLASSES];
    __shared__ float lse_sh;
    int t = threadIdx.x;  // 64 threads
    p[t] = g_pooled[t] * (1.0f / (float)N_NODES);
    __syncthreads();
    if (t < NUM_CLASSES) {
        float s = fc_b[t];
#pragma unroll
        for (int c = 0; c < OUT_C; c++) s += p[c] * fc_w[c * NUM_CLASSES + t];
        lg[t] = s;
    }
    __syncthreads();
    if (t == 0) {
        float mx = lg[0];
        for (int j = 1; j < NUM_CLASSES; j++) mx = fmaxf(mx, lg[j]);
        float se = 0.f;
        for (int j = 0; j < NUM_CLASSES; j++) se += expf(lg[j] - mx);
        lse_sh = mx + logf(se);
    }
    __syncthreads();
    if (t < NUM_CLASSES) out[t] = lg[t] - lse_sh;
}

// ----------------------------------------------------------------------------
// launch
// ----------------------------------------------------------------------------
extern "C" void kernel_launch(void* const* d_in, const int* in_sizes, int n_in,
                              void* d_out, int out_size) {
    const float* x      = (const float*)d_in[0];
    const void*  ei     = d_in[1];
    const float* W1     = (const float*)d_in[2];
    const float* att_s1 = (const float*)d_in[3];
    const float* att_d1 = (const float*)d_in[4];
    const float* b1     = (const float*)d_in[5];
    const float* W2     = (const float*)d_in[6];
    const float* att_s2 = (const float*)d_in[7];
    const float* att_d2 = (const float*)d_in[8];
    const float* b2     = (const float*)d_in[9];
    const float* fc_w   = (const float*)d_in[10];
    const float* fc_b   = (const float*)d_in[11];
    float* out = (float*)d_out;

    int E = in_sizes[1] / 2;
    if (E > E_MAX) E = E_MAX;

    const int WARPS_PER_BLOCK = 8;
    const int nodeBlocks = (N_NODES + WARPS_PER_BLOCK - 1) / WARPS_PER_BLOCK;
    const int mBlocks = (N_NODES + 127) / 128;

    zero_kernel<<<(N_NODES + 256) / 256, 256>>>();
    detect_kernel<<<1, 256>>>((const int*)ei);
    convert_count_kernel<<<(E + 255) / 256, 256>>>(ei, E);
    scan1_kernel<<<SCAN_NBLK, SCAN_BLOCK>>>();
    scan2_kernel<<<1, 64>>>();
    scan3_kernel<<<SCAN_NBLK, SCAN_BLOCK>>>();
    fill_kernel<<<(E + 255) / 256, 256>>>(E);

    // Layer 1: fused 3xFP16 HMMA GEMM + fp16 convert + alpha logits
    gemm1_fused<<<dim3(F1 / 128, mBlocks), 256>>>(x, W1, att_s1, att_d1);
    agg1_kernel<<<nodeBlocks, 256>>>(b1);

    // Layer 2: fused 3xFP16 HMMA GEMM + fp16 convert + alpha logits
    gemm2_fused<<<dim3(1, mBlocks), 128>>>(W2, att_s2, att_d2);
    agg2_pool_kernel<<<nodeBlocks, 256>>>(b2);

    // Head
    final_kernel<<<1, 64>>>(fc_w, fc_b, out);
}

// round 8
// speedup vs baseline: 2.1069x; 1.0723x over previous
#include <cuda_runtime.h>
#include <cuda_bf16.h>
#include <cuda_fp16.h>
#include <math.h>

// Problem constants (fixed by the reference)
#define N_NODES 50000
#define E_MAX   800000
#define IN_C    128
#define HID     64
#define HEADS   4
#define F1      (HEADS*HID)   // 256
#define OUT_C   64
#define NUM_CLASSES 40

#define SCAN_BLOCK 1024
#define SCAN_NBLK  ((N_NODES + SCAN_BLOCK - 1) / SCAN_BLOCK)   // 49

// ----------------------------------------------------------------------------
// Scratch (device globals: allocation-free per harness rules)
// ----------------------------------------------------------------------------
__device__ __half g_h1h[(size_t)N_NODES * F1];   // layer-1 features (fp16 gather)
__device__ __half g_x2h[(size_t)N_NODES * F1];   // layer-1 GAT output, fp16
__device__ __half g_h2h[(size_t)N_NODES * OUT_C];// layer-2 features (fp16 gather)
__device__ float  g_as1[N_NODES * HEADS];
__device__ float  g_ad1[N_NODES * HEADS];
__device__ float  g_as2[N_NODES];
__device__ float  g_ad2[N_NODES];
__device__ int    g_counts[N_NODES + 1];
__device__ int    g_rowptr[N_NODES + 1];
__device__ int    g_cursor[N_NODES];
__device__ int    g_src32[E_MAX];
__device__ int    g_dst32[E_MAX];
__device__ int    g_csr_src[E_MAX];
__device__ int    g_blksum[SCAN_NBLK];
__device__ int    g_blkoff[SCAN_NBLK];
__device__ float  g_pooled[OUT_C];
__device__ int    g_is64;

__device__ __forceinline__ float lrelu(float v) { return v > 0.f ? v : 0.2f * v; }

__device__ __forceinline__ void split_h(float v, __half& hi, __half& lo) {
    hi = __float2half(v);
    lo = __float2half(v - __half2float(hi));
}

// m16n8k16 fp16 MMA, fp32 accumulate
__device__ __forceinline__ void mma_f16(float* c, const unsigned* a, const unsigned* b) {
    asm volatile(
        "mma.sync.aligned.m16n8k16.row.col.f32.f16.f16.f32 "
        "{%0,%1,%2,%3}, {%4,%5,%6,%7}, {%8,%9}, {%0,%1,%2,%3};\n"
        : "+f"(c[0]), "+f"(c[1]), "+f"(c[2]), "+f"(c[3])
        : "r"(a[0]), "r"(a[1]), "r"(a[2]), "r"(a[3]), "r"(b[0]), "r"(b[1]));
}

// ----------------------------------------------------------------------------
// 0+1) init (zero counts + pooled) and int64/int32 detection, one launch
// ----------------------------------------------------------------------------
__global__ void init_detect_kernel(const int* __restrict__ ei) {
    int i = blockIdx.x * blockDim.x + threadIdx.x;
    if (i < N_NODES + 1) g_counts[i] = 0;
    if (i < OUT_C)       g_pooled[i] = 0.f;
    if (blockIdx.x == 0) {
        __shared__ int any;
        if (threadIdx.x == 0) any = 0;
        __syncthreads();
        for (int j = threadIdx.x; j < 4096; j += blockDim.x) {
            if (ei[2 * j + 1] != 0) any = 1;
        }
        __syncthreads();
        if (threadIdx.x == 0) g_is64 = (any == 0) ? 1 : 0;
    }
}

// ----------------------------------------------------------------------------
// 2) convert to int32 + count in-degrees
// ----------------------------------------------------------------------------
__global__ void convert_count_kernel(const void* __restrict__ ei, int E) {
    int e = blockIdx.x * blockDim.x + threadIdx.x;
    if (e >= E) return;
    int s, d;
    if (g_is64) {
        const long long* p = (const long long*)ei;
        s = (int)p[e]; d = (int)p[E + e];
    } else {
        const int* p = (const int*)ei;
        s = p[e]; d = p[E + e];
    }
    g_src32[e] = s;
    g_dst32[e] = d;
    atomicAdd(&g_counts[d], 1);
}

// ----------------------------------------------------------------------------
// 3) parallel exclusive scan of g_counts -> g_rowptr / g_cursor  (PROVEN r4)
// ----------------------------------------------------------------------------
__global__ void __launch_bounds__(SCAN_BLOCK) scan1_kernel() {
    int i = blockIdx.x * SCAN_BLOCK + threadIdx.x;
    int v = (i < N_NODES) ? g_counts[i] : 0;
    __shared__ int sh[32];
    int lane = threadIdx.x & 31, w = threadIdx.x >> 5;
#pragma unroll
    for (int o = 16; o; o >>= 1) v += __shfl_xor_sync(~0u, v, o);
    if (lane == 0) sh[w] = v;
    __syncthreads();
    if (w == 0) {
        int s = sh[lane];
#pragma unroll
        for (int o = 16; o; o >>= 1) s += __shfl_xor_sync(~0u, s, o);
        if (lane == 0) g_blksum[blockIdx.x] = s;
    }
}

__global__ void scan2_kernel() {
    __shared__ int s[64];
    int t = threadIdx.x;
    int v = (t < SCAN_NBLK) ? g_blksum[t] : 0;
    s[t] = v;
    __syncthreads();
#pragma unroll
    for (int o = 1; o < 64; o <<= 1) {
        int u = (t >= o) ? s[t - o] : 0;
        __syncthreads();
        s[t] += u;
        __syncthreads();
    }
    if (t < SCAN_NBLK) g_blkoff[t] = s[t] - v;
    if (t == SCAN_NBLK - 1) g_rowptr[N_NODES] = s[t];
}

__global__ void __launch_bounds__(SCAN_BLOCK) scan3_kernel() {
    int b = blockIdx.x, t = threadIdx.x;
    int i = b * SCAN_BLOCK + t;
    int v = (i < N_NODES) ? g_counts[i] : 0;
    int lane = t & 31, w = t >> 5;
    int inc = v;
#pragma unroll
    for (int o = 1; o < 32; o <<= 1) {
        int u = __shfl_up_sync(~0u, inc, o);
        if (lane >= o) inc += u;
    }
    __shared__ int wsum[32];
    if (lane == 31) wsum[w] = inc;
    __syncthreads();
    if (w == 0) {
        int s = wsum[lane];
#pragma unroll
        for (int o = 1; o < 32; o <<= 1) {
            int u = __shfl_up_sync(~0u, s, o);
            if (lane >= o) s += u;
        }
        wsum[lane] = s;
    }
    __syncthreads();
    int exc = inc - v + (w > 0 ? wsum[w - 1] : 0) + g_blkoff[b];
    if (i < N_NODES) {
        g_rowptr[i] = exc;
        g_cursor[i] = exc;
    }
}

// ----------------------------------------------------------------------------
// 4) fill CSR (src indices grouped by dst)
// ----------------------------------------------------------------------------
__global__ void fill_kernel(int E) {
    int e = blockIdx.x * blockDim.x + threadIdx.x;
    if (e >= E) return;
    int pos = atomicAdd(&g_cursor[g_dst32[e]], 1);
    g_csr_src[pos] = g_src32[e];
}

// ----------------------------------------------------------------------------
// GEMM1 fused (3xFP16 HMMA): h1 = x @ W1  (50000x128 @ 128x256)  (PROVEN r7)
// ----------------------------------------------------------------------------
__global__ void __launch_bounds__(256) gemm1_fused(const float* __restrict__ A,
                                                   const float* __restrict__ B,
                                                   const float* __restrict__ att_s,
                                                   const float* __restrict__ att_d) {
    constexpr int M = N_NODES, N = F1, K = IN_C;
    constexpr int BM = 128, BN = 128, BK = 32;
    constexpr int SKA = BK + 8;
    __shared__ __half Ah[BM][SKA], Al[BM][SKA];
    __shared__ __half BhT[BN][SKA], BlT[BN][SKA];
    __shared__ float satt_s[BN], satt_d[BN];

    const int tid = threadIdx.x;
    const int lane = tid & 31, warp = tid >> 5;
    const int g = lane >> 2, t = lane & 3;
    const int warp_m = warp & 3;
    const int warp_n = warp >> 2;
    const int block_row = blockIdx.y * BM;
    const int block_col = blockIdx.x * BN;

    if (tid < BN) {
        satt_s[tid] = att_s[block_col + tid];
        satt_d[tid] = att_d[block_col + tid];
    }

    float acc[2][8][4];
#pragma unroll
    for (int mt = 0; mt < 2; mt++)
#pragma unroll
        for (int nt = 0; nt < 8; nt++)
#pragma unroll
            for (int q = 0; q < 4; q++) acc[mt][nt][q] = 0.f;

    for (int k0 = 0; k0 < K; k0 += BK) {
#pragma unroll
        for (int it = 0; it < 4; it++) {
            int idx = tid + it * 256;
            int r  = idx >> 3;
            int c4 = idx & 7;
            int gr = block_row + r;
            float4 v = make_float4(0.f, 0.f, 0.f, 0.f);
            if (gr < M) v = *(const float4*)(A + (size_t)gr * K + k0 + c4 * 4);
            __half h0, l0, h1, l1, h2, l2, h3, l3;
            split_h(v.x, h0, l0); split_h(v.y, h1, l1);
            split_h(v.z, h2, l2); split_h(v.w, h3, l3);
            int c = c4 * 4;
            Ah[r][c + 0] = h0; Ah[r][c + 1] = h1; Ah[r][c + 2] = h2; Ah[r][c + 3] = h3;
            Al[r][c + 0] = l0; Al[r][c + 1] = l1; Al[r][c + 2] = l2; Al[r][c + 3] = l3;
        }
        {
            int n  = tid & 127;
            int kb = (tid >> 7) * 16;
#pragma unroll
            for (int i = 0; i < 16; i++) {
                int k = kb + i;
                float v = B[(size_t)(k0 + k) * N + block_col + n];
                __half h, l; split_h(v, h, l);
                BhT[n][k] = h; BlT[n][k] = l;
            }
        }
        __syncthreads();
#pragma unroll
        for (int ks = 0; ks < 2; ks++) {
            const int kk = ks * 16;
            unsigned ah[2][4], al[2][4];
#pragma unroll
            for (int mt = 0; mt < 2; mt++) {
                int r0 = warp_m * 32 + mt * 16 + g;
                ah[mt][0] = *(const unsigned*)&Ah[r0][kk + 2 * t];
                ah[mt][1] = *(const unsigned*)&Ah[r0 + 8][kk + 2 * t];
                ah[mt][2] = *(const unsigned*)&Ah[r0][kk + 2 * t + 8];
                ah[mt][3] = *(const unsigned*)&Ah[r0 + 8][kk + 2 * t + 8];
                al[mt][0] = *(const unsigned*)&Al[r0][kk + 2 * t];
                al[mt][1] = *(const unsigned*)&Al[r0 + 8][kk + 2 * t];
                al[mt][2] = *(const unsigned*)&Al[r0][kk + 2 * t + 8];
                al[mt][3] = *(const unsigned*)&Al[r0 + 8][kk + 2 * t + 8];
            }
#pragma unroll
            for (int nt = 0; nt < 8; nt++) {
                int n0 = warp_n * 64 + nt * 8 + g;
                unsigned bh[2], bl[2];
                bh[0] = *(const unsigned*)&BhT[n0][kk + 2 * t];
                bh[1] = *(const unsigned*)&BhT[n0][kk + 2 * t + 8];
                bl[0] = *(const unsigned*)&BlT[n0][kk + 2 * t];
                bl[1] = *(const unsigned*)&BlT[n0][kk + 2 * t + 8];
#pragma unroll
                for (int mt = 0; mt < 2; mt++) {
                    mma_f16(acc[mt][nt], ah[mt], bl);
                    mma_f16(acc[mt][nt], al[mt], bh);
                    mma_f16(acc[mt][nt], ah[mt], bh);
                }
            }
        }
        __syncthreads();
    }

    const int head = blockIdx.x * 2 + warp_n;
#pragma unroll
    for (int mt = 0; mt < 2; mt++) {
#pragma unroll
        for (int rr = 0; rr < 2; rr++) {
            int grow = block_row + warp_m * 32 + mt * 16 + g + rr * 8;
            bool valid = grow < M;
            float as_p = 0.f, ad_p = 0.f;
#pragma unroll
            for (int nt = 0; nt < 8; nt++) {
                float v0 = acc[mt][nt][rr * 2 + 0];
                float v1 = acc[mt][nt][rr * 2 + 1];
                int col = warp_n * 64 + nt * 8 + 2 * t;
                as_p += v0 * satt_s[col] + v1 * satt_s[col + 1];
                ad_p += v0 * satt_d[col] + v1 * satt_d[col + 1];
                if (valid) {
                    __half2 hv = __floats2half2_rn(v0, v1);
                    *(__half2*)&g_h1h[(size_t)grow * F1 + block_col + col] = hv;
                }
            }
            as_p += __shfl_xor_sync(0xffffffffu, as_p, 1);
            as_p += __shfl_xor_sync(0xffffffffu, as_p, 2);
            ad_p += __shfl_xor_sync(0xffffffffu, ad_p, 1);
            ad_p += __shfl_xor_sync(0xffffffffu, ad_p, 2);
            if (t == 0 && valid) {
                g_as1[grow * HEADS + head] = as_p;
                g_ad1[grow * HEADS + head] = ad_p;
            }
        }
    }
}

// ----------------------------------------------------------------------------
// GEMM2 fused (2xFP16 HMMA, exact fp16 A): h2 = x2h @ W2  (50000x256 @ 256x64)
// A is already fp16 (exact) -> no A split; B split hi/lo -> 2 MMAs.
// BM=128, BN=64, BK=32. 4 warps along M; warp tile 32x64.
// ----------------------------------------------------------------------------
__global__ void __launch_bounds__(128) gemm2_fused(const float* __restrict__ B,
                                                   const float* __restrict__ att_s,
                                                   const float* __restrict__ att_d) {
    constexpr int M = N_NODES, N = OUT_C, K = F1;
    constexpr int BM = 128, BN = 64, BK = 32;
    constexpr int SKA = BK + 8;
    const __half* A = g_x2h;
    __shared__ __half Ah[BM][SKA];
    __shared__ __half BhT[BN][SKA], BlT[BN][SKA];
    __shared__ float satt_s[BN], satt_d[BN];

    const int tid = threadIdx.x;
    const int lane = tid & 31, warp = tid >> 5;
    const int g = lane >> 2, t = lane & 3;
    const int block_row = blockIdx.y * BM;

    if (tid < BN) {
        satt_s[tid] = att_s[tid];
        satt_d[tid] = att_d[tid];
    }

    float acc[2][8][4];
#pragma unroll
    for (int mt = 0; mt < 2; mt++)
#pragma unroll
        for (int nt = 0; nt < 8; nt++)
#pragma unroll
            for (int q = 0; q < 4; q++) acc[mt][nt][q] = 0.f;

    for (int k0 = 0; k0 < K; k0 += BK) {
        // A tile 128x32 halves = 512 uint4; 128 thr x 4
#pragma unroll
        for (int it = 0; it < 4; it++) {
            int idx = tid + it * 128;
            int r  = idx >> 2;           // 4 uint4 per row
            int c8 = idx & 3;            // 8 halves each
            int gr = block_row + r;
            uint4 v = make_uint4(0u, 0u, 0u, 0u);
            if (gr < M) v = *(const uint4*)(A + (size_t)gr * K + k0 + c8 * 8);
            *(uint4*)&Ah[r][c8 * 8] = v;
        }
        // B tile 32x64 fp32 -> transposed hi/lo
        {
            int n  = tid & 63;
            int kb = (tid >> 6) * 16;
#pragma unroll
            for (int i = 0; i < 16; i++) {
                int k = kb + i;
                float v = B[(size_t)(k0 + k) * N + n];
                __half h, l; split_h(v, h, l);
                BhT[n][k] = h; BlT[n][k] = l;
            }
        }
        __syncthreads();
#pragma unroll
        for (int ks = 0; ks < 2; ks++) {
            const int kk = ks * 16;
            unsigned ah[2][4];
#pragma unroll
            for (int mt = 0; mt < 2; mt++) {
                int r0 = warp * 32 + mt * 16 + g;
                ah[mt][0] = *(const unsigned*)&Ah[r0][kk + 2 * t];
                ah[mt][1] = *(const unsigned*)&Ah[r0 + 8][kk + 2 * t];
                ah[mt][2] = *(const unsigned*)&Ah[r0][kk + 2 * t + 8];
                ah[mt][3] = *(const unsigned*)&Ah[r0 + 8][kk + 2 * t + 8];
            }
#pragma unroll
            for (int nt = 0; nt < 8; nt++) {
                int n0 = nt * 8 + g;
                unsigned bh[2], bl[2];
                bh[0] = *(const unsigned*)&BhT[n0][kk + 2 * t];
                bh[1] = *(const unsigned*)&BhT[n0][kk + 2 * t + 8];
                bl[0] = *(const unsigned*)&BlT[n0][kk + 2 * t];
                bl[1] = *(const unsigned*)&BlT[n0][kk + 2 * t + 8];
#pragma unroll
                for (int mt = 0; mt < 2; mt++) {
                    mma_f16(acc[mt][nt], ah[mt], bl);
                    mma_f16(acc[mt][nt], ah[mt], bh);
                }
            }
        }
        __syncthreads();
    }

#pragma unroll
    for (int mt = 0; mt < 2; mt++) {
#pragma unroll
        for (int rr = 0; rr < 2; rr++) {
            int grow = block_row + warp * 32 + mt * 16 + g + rr * 8;
            bool valid = grow < M;
            float as_p = 0.f, ad_p = 0.f;
#pragma unroll
            for (int nt = 0; nt < 8; nt++) {
                float v0 = acc[mt][nt][rr * 2 + 0];
                float v1 = acc[mt][nt][rr * 2 + 1];
                int col = nt * 8 + 2 * t;
                as_p += v0 * satt_s[col] + v1 * satt_s[col + 1];
                ad_p += v0 * satt_d[col] + v1 * satt_d[col + 1];
                if (valid) {
                    __half2 hv = __floats2half2_rn(v0, v1);
                    *(__half2*)&g_h2h[(size_t)grow * OUT_C + col] = hv;
                }
            }
            as_p += __shfl_xor_sync(0xffffffffu, as_p, 1);
            as_p += __shfl_xor_sync(0xffffffffu, as_p, 2);
            ad_p += __shfl_xor_sync(0xffffffffu, ad_p, 1);
            ad_p += __shfl_xor_sync(0xffffffffu, ad_p, 2);
            if (t == 0 && valid) {
                g_as2[grow] = as_p;
                g_ad2[grow] = ad_p;
            }
        }
    }
}

// ----------------------------------------------------------------------------
// Layer-1 aggregation: warp per dst node, single-pass softmax, fp16 gathers,
// fp32 accumulation. Fuses +b1 and relu. Output x2 now fp16.
// ----------------------------------------------------------------------------
__global__ void agg1_kernel(const float* __restrict__ b1) {
    int t = threadIdx.x;
    int warp = (blockIdx.x * blockDim.x + t) >> 5;
    if (warp >= N_NODES) return;
    int lane = t & 31;
    int d = warp;
    int head = lane >> 3;

    float ad = g_ad1[d * HEADS + head];
    int beg = g_rowptr[d], end = g_rowptr[d + 1];

    float denom = 1e-16f;
    float acc[8] = {0.f, 0.f, 0.f, 0.f, 0.f, 0.f, 0.f, 0.f};
    for (int i = beg; i < end; i++) {
        int s = g_csr_src[i];
        float w = __expf(lrelu(g_as1[s * HEADS + head] + ad));
        denom += w;
        uint4 u = *(const uint4*)&g_h1h[(size_t)s * F1 + lane * 8];
        float2 f0 = __half22float2(*reinterpret_cast<__half2*>(&u.x));
        float2 f1 = __half22float2(*reinterpret_cast<__half2*>(&u.y));
        float2 f2 = __half22float2(*reinterpret_cast<__half2*>(&u.z));
        float2 f3 = __half22float2(*reinterpret_cast<__half2*>(&u.w));
        acc[0] += w * f0.x; acc[1] += w * f0.y;
        acc[2] += w * f1.x; acc[3] += w * f1.y;
        acc[4] += w * f2.x; acc[5] += w * f2.y;
        acc[6] += w * f3.x; acc[7] += w * f3.y;
    }
    {   // self loop
        float w = __expf(lrelu(g_as1[d * HEADS + head] + ad));
        denom += w;
        uint4 u = *(const uint4*)&g_h1h[(size_t)d * F1 + lane * 8];
        float2 f0 = __half22float2(*reinterpret_cast<__half2*>(&u.x));
        float2 f1 = __half22float2(*reinterpret_cast<__half2*>(&u.y));
        float2 f2 = __half22float2(*reinterpret_cast<__half2*>(&u.z));
        float2 f3 = __half22float2(*reinterpret_cast<__half2*>(&u.w));
        acc[0] += w * f0.x; acc[1] += w * f0.y;
        acc[2] += w * f1.x; acc[3] += w * f1.y;
        acc[4] += w * f2.x; acc[5] += w * f2.y;
        acc[6] += w * f3.x; acc[7] += w * f3.y;
    }
    float inv = 1.f / denom;
    int cb = lane * 8;
    __half hbuf[8];
#pragma unroll
    for (int j = 0; j < 8; j++)
        hbuf[j] = __float2half(fmaxf(acc[j] * inv + b1[cb + j], 0.f));
    *(uint4*)&g_x2h[(size_t)d * F1 + cb] = *(uint4*)hbuf;
}

// ----------------------------------------------------------------------------
// Layer-2 aggregation (heads=1) + bias + relu + global mean-pool accumulation.
// ----------------------------------------------------------------------------
__global__ void agg2_pool_kernel(const float* __restrict__ b2) {
    __shared__ float sp[OUT_C];
    int t = threadIdx.x;
    if (t < OUT_C) sp[t] = 0.f;
    __syncthreads();

    int warp = (blockIdx.x * blockDim.x + t) >> 5;
    int lane = t & 31;
    if (warp < N_NODES) {
        int d = warp;
        float ad = g_ad2[d];
        int beg = g_rowptr[d], end = g_rowptr[d + 1];

        float denom = 1e-16f;
        float a0 = 0.f, a1 = 0.f;
        for (int i = beg; i < end; i++) {
            int s = g_csr_src[i];
            float w = __expf(lrelu(g_as2[s] + ad));
            denom += w;
            a0 += w * __half2float(g_h2h[(size_t)s * OUT_C + lane]);
            a1 += w * __half2float(g_h2h[(size_t)s * OUT_C + 32 + lane]);
        }
        {
            float w = __expf(lrelu(g_as2[d] + ad));
            denom += w;
            a0 += w * __half2float(g_h2h[(size_t)d * OUT_C + lane]);
            a1 += w * __half2float(g_h2h[(size_t)d * OUT_C + 32 + lane]);
        }
        float inv = 1.f / denom;
        float v0 = fmaxf(a0 * inv + b2[lane], 0.f);
        float v1 = fmaxf(a1 * inv + b2[32 + lane], 0.f);
        atomicAdd(&sp[lane], v0);
        atomicAdd(&sp[32 + lane], v1);
    }
    __syncthreads();
    if (t < OUT_C) atomicAdd(&g_pooled[t], sp[t]);
}

// ----------------------------------------------------------------------------
// Final: mean-pool scale, FC to 40 classes, log_softmax
// ----------------------------------------------------------------------------
__global__ void final_kernel(const float* __restrict__ fc_w,
                             const float* __restrict__ fc_b,
                             float* __restrict__ out) {
    __shared__ float p[OUT_C];
    __shared__ float lg[NUM_CLASSES];
    __shared__ float lse_sh;
    int t = threadIdx.x;  // 64 threads
    p[t] = g_pooled[t] * (1.0f / (float)N_NODES);
    __syncthreads();
    if (t < NUM_CLASSES) {
        float s = fc_b[t];
#pragma unroll
        for (int c = 0; c < OUT_C; c++) s += p[c] * fc_w[c * NUM_CLASSES + t];
        lg[t] = s;
    }
    __syncthreads();
    if (t == 0) {
        float mx = lg[0];
        for (int j = 1; j < NUM_CLASSES; j++) mx = fmaxf(mx, lg[j]);
        float se = 0.f;
        for (int j = 0; j < NUM_CLASSES; j++) se += expf(lg[j] - mx);
        lse_sh = mx + logf(se);
    }
    __syncthreads();
    if (t < NUM_CLASSES) out[t] = lg[t] - lse_sh;
}

// ----------------------------------------------------------------------------
// launch
// ----------------------------------------------------------------------------
extern "C" void kernel_launch(void* const* d_in, const int* in_sizes, int n_in,
                              void* d_out, int out_size) {
    const float* x      = (const float*)d_in[0];
    const void*  ei     = d_in[1];
    const float* W1     = (const float*)d_in[2];
    const float* att_s1 = (const float*)d_in[3];
    const float* att_d1 = (const float*)d_in[4];
    const float* b1     = (const float*)d_in[5];
    const float* W2     = (const float*)d_in[6];
    const float* att_s2 = (const float*)d_in[7];
    const float* att_d2 = (const float*)d_in[8];
    const float* b2     = (const float*)d_in[9];
    const float* fc_w   = (const float*)d_in[10];
    const float* fc_b   = (const float*)d_in[11];
    float* out = (float*)d_out;

    int E = in_sizes[1] / 2;
    if (E > E_MAX) E = E_MAX;

    const int WARPS_PER_BLOCK = 8;
    const int nodeBlocks = (N_NODES + WARPS_PER_BLOCK - 1) / WARPS_PER_BLOCK;
    const int mBlocks = (N_NODES + 127) / 128;

    init_detect_kernel<<<(N_NODES + 256) / 256, 256>>>((const int*)ei);
    convert_count_kernel<<<(E + 255) / 256, 256>>>(ei, E);
    scan1_kernel<<<SCAN_NBLK, SCAN_BLOCK>>>();
    scan2_kernel<<<1, 64>>>();
    scan3_kernel<<<SCAN_NBLK, SCAN_BLOCK>>>();
    fill_kernel<<<(E + 255) / 256, 256>>>(E);

    // Layer 1: fused 3xFP16 HMMA GEMM + fp16 convert + alpha logits
    gemm1_fused<<<dim3(F1 / 128, mBlocks), 256>>>(x, W1, att_s1, att_d1);
    agg1_kernel<<<nodeBlocks, 256>>>(b1);

    // Layer 2: fused 2xFP16 HMMA GEMM (fp16-exact A) + alpha logits
    gemm2_fused<<<dim3(1, mBlocks), 128>>>(W2, att_s2, att_d2);
    agg2_pool_kernel<<<nodeBlocks, 256>>>(b2);

    // Head
    final_kernel<<<1, 64>>>(fc_w, fc_b, out);
}

// round 9
// speedup vs baseline: 2.2562x; 1.0708x over previous
#include <cuda_runtime.h>
#include <cuda_bf16.h>
#include <cuda_fp16.h>
#include <math.h>

// Problem constants (fixed by the reference)
#define N_NODES 50000
#define E_MAX   800000
#define IN_C    128
#define HID     64
#define HEADS   4
#define F1      (HEADS*HID)   // 256
#define OUT_C   64
#define NUM_CLASSES 40

#define SCAN_BLOCK 1024
#define SCAN_NBLK  ((N_NODES + SCAN_BLOCK - 1) / SCAN_BLOCK)   // 49

// ----------------------------------------------------------------------------
// Scratch (device globals: allocation-free per harness rules)
// ----------------------------------------------------------------------------
__device__ __half g_h1h[(size_t)N_NODES * F1];   // layer-1 features (fp16 gather)
__device__ __half g_x2h[(size_t)N_NODES * F1];   // layer-1 GAT output, fp16
__device__ __half g_h2h[(size_t)N_NODES * OUT_C];// layer-2 features (fp16 gather)
__device__ float  g_as1[N_NODES * HEADS];
__device__ float  g_ad1[N_NODES * HEADS];
__device__ float  g_as2[N_NODES];
__device__ float  g_ad2[N_NODES];
__device__ int    g_counts[N_NODES + 1];
__device__ int    g_rowptr[N_NODES + 1];
__device__ int    g_cursor[N_NODES];
__device__ int    g_src32[E_MAX];
__device__ int    g_dst32[E_MAX];
__device__ int    g_csr_src[E_MAX];
__device__ int    g_blksum[SCAN_NBLK];
__device__ int    g_blkoff[SCAN_NBLK];
__device__ float  g_pooled[OUT_C];
__device__ int    g_is64;

__device__ __forceinline__ float lrelu(float v) { return v > 0.f ? v : 0.2f * v; }

__device__ __forceinline__ void split_h(float v, __half& hi, __half& lo) {
    hi = __float2half(v);
    lo = __float2half(v - __half2float(hi));
}

// m16n8k16 fp16 MMA, fp32 accumulate
__device__ __forceinline__ void mma_f16(float* c, const unsigned* a, const unsigned* b) {
    asm volatile(
        "mma.sync.aligned.m16n8k16.row.col.f32.f16.f16.f32 "
        "{%0,%1,%2,%3}, {%4,%5,%6,%7}, {%8,%9}, {%0,%1,%2,%3};\n"
        : "+f"(c[0]), "+f"(c[1]), "+f"(c[2]), "+f"(c[3])
        : "r"(a[0]), "r"(a[1]), "r"(a[2]), "r"(a[3]), "r"(b[0]), "r"(b[1]));
}

// ----------------------------------------------------------------------------
// 0+1) init (zero counts + pooled) and int64/int32 detection, one launch
// ----------------------------------------------------------------------------
__global__ void init_detect_kernel(const int* __restrict__ ei) {
    int i = blockIdx.x * blockDim.x + threadIdx.x;
    if (i < N_NODES + 1) g_counts[i] = 0;
    if (i < OUT_C)       g_pooled[i] = 0.f;
    if (blockIdx.x == 0) {
        __shared__ int any;
        if (threadIdx.x == 0) any = 0;
        __syncthreads();
        for (int j = threadIdx.x; j < 4096; j += blockDim.x) {
            if (ei[2 * j + 1] != 0) any = 1;
        }
        __syncthreads();
        if (threadIdx.x == 0) g_is64 = (any == 0) ? 1 : 0;
    }
}

// ----------------------------------------------------------------------------
// 2) convert to int32 + count in-degrees
// ----------------------------------------------------------------------------
__global__ void convert_count_kernel(const void* __restrict__ ei, int E) {
    int e = blockIdx.x * blockDim.x + threadIdx.x;
    if (e >= E) return;
    int s, d;
    if (g_is64) {
        const long long* p = (const long long*)ei;
        s = (int)p[e]; d = (int)p[E + e];
    } else {
        const int* p = (const int*)ei;
        s = p[e]; d = p[E + e];
    }
    g_src32[e] = s;
    g_dst32[e] = d;
    atomicAdd(&g_counts[d], 1);
}

// ----------------------------------------------------------------------------
// 3) parallel exclusive scan of g_counts -> g_rowptr / g_cursor  (PROVEN r4)
// ----------------------------------------------------------------------------
__global__ void __launch_bounds__(SCAN_BLOCK) scan1_kernel() {
    int i = blockIdx.x * SCAN_BLOCK + threadIdx.x;
    int v = (i < N_NODES) ? g_counts[i] : 0;
    __shared__ int sh[32];
    int lane = threadIdx.x & 31, w = threadIdx.x >> 5;
#pragma unroll
    for (int o = 16; o; o >>= 1) v += __shfl_xor_sync(~0u, v, o);
    if (lane == 0) sh[w] = v;
    __syncthreads();
    if (w == 0) {
        int s = sh[lane];
#pragma unroll
        for (int o = 16; o; o >>= 1) s += __shfl_xor_sync(~0u, s, o);
        if (lane == 0) g_blksum[blockIdx.x] = s;
    }
}

__global__ void scan2_kernel() {
    __shared__ int s[64];
    int t = threadIdx.x;
    int v = (t < SCAN_NBLK) ? g_blksum[t] : 0;
    s[t] = v;
    __syncthreads();
#pragma unroll
    for (int o = 1; o < 64; o <<= 1) {
        int u = (t >= o) ? s[t - o] : 0;
        __syncthreads();
        s[t] += u;
        __syncthreads();
    }
    if (t < SCAN_NBLK) g_blkoff[t] = s[t] - v;
    if (t == SCAN_NBLK - 1) g_rowptr[N_NODES] = s[t];
}

__global__ void __launch_bounds__(SCAN_BLOCK) scan3_kernel() {
    int b = blockIdx.x, t = threadIdx.x;
    int i = b * SCAN_BLOCK + t;
    int v = (i < N_NODES) ? g_counts[i] : 0;
    int lane = t & 31, w = t >> 5;
    int inc = v;
#pragma unroll
    for (int o = 1; o < 32; o <<= 1) {
        int u = __shfl_up_sync(~0u, inc, o);
        if (lane >= o) inc += u;
    }
    __shared__ int wsum[32];
    if (lane == 31) wsum[w] = inc;
    __syncthreads();
    if (w == 0) {
        int s = wsum[lane];
#pragma unroll
        for (int o = 1; o < 32; o <<= 1) {
            int u = __shfl_up_sync(~0u, s, o);
            if (lane >= o) s += u;
        }
        wsum[lane] = s;
    }
    __syncthreads();
    int exc = inc - v + (w > 0 ? wsum[w - 1] : 0) + g_blkoff[b];
    if (i < N_NODES) {
        g_rowptr[i] = exc;
        g_cursor[i] = exc;
    }
}

// ----------------------------------------------------------------------------
// 4) fill CSR (src indices grouped by dst)
// ----------------------------------------------------------------------------
__global__ void fill_kernel(int E) {
    int e = blockIdx.x * blockDim.x + threadIdx.x;
    if (e >= E) return;
    int pos = atomicAdd(&g_cursor[g_dst32[e]], 1);
    g_csr_src[pos] = g_src32[e];
}

// ----------------------------------------------------------------------------
// GEMM1 fused (3xFP16 HMMA): h1 = x @ W1  (50000x128 @ 128x256)  (PROVEN r7)
// ----------------------------------------------------------------------------
__global__ void __launch_bounds__(256) gemm1_fused(const float* __restrict__ A,
                                                   const float* __restrict__ B,
                                                   const float* __restrict__ att_s,
                                                   const float* __restrict__ att_d) {
    constexpr int M = N_NODES, N = F1, K = IN_C;
    constexpr int BM = 128, BN = 128, BK = 32;
    constexpr int SKA = BK + 8;
    __shared__ __half Ah[BM][SKA], Al[BM][SKA];
    __shared__ __half BhT[BN][SKA], BlT[BN][SKA];
    __shared__ float satt_s[BN], satt_d[BN];

    const int tid = threadIdx.x;
    const int lane = tid & 31, warp = tid >> 5;
    const int g = lane >> 2, t = lane & 3;
    const int warp_m = warp & 3;
    const int warp_n = warp >> 2;
    const int block_row = blockIdx.y * BM;
    const int block_col = blockIdx.x * BN;

    if (tid < BN) {
        satt_s[tid] = att_s[block_col + tid];
        satt_d[tid] = att_d[block_col + tid];
    }

    float acc[2][8][4];
#pragma unroll
    for (int mt = 0; mt < 2; mt++)
#pragma unroll
        for (int nt = 0; nt < 8; nt++)
#pragma unroll
            for (int q = 0; q < 4; q++) acc[mt][nt][q] = 0.f;

    for (int k0 = 0; k0 < K; k0 += BK) {
#pragma unroll
        for (int it = 0; it < 4; it++) {
            int idx = tid + it * 256;
            int r  = idx >> 3;
            int c4 = idx & 7;
            int gr = block_row + r;
            float4 v = make_float4(0.f, 0.f, 0.f, 0.f);
            if (gr < M) v = *(const float4*)(A + (size_t)gr * K + k0 + c4 * 4);
            __half h0, l0, h1, l1, h2, l2, h3, l3;
            split_h(v.x, h0, l0); split_h(v.y, h1, l1);
            split_h(v.z, h2, l2); split_h(v.w, h3, l3);
            int c = c4 * 4;
            Ah[r][c + 0] = h0; Ah[r][c + 1] = h1; Ah[r][c + 2] = h2; Ah[r][c + 3] = h3;
            Al[r][c + 0] = l0; Al[r][c + 1] = l1; Al[r][c + 2] = l2; Al[r][c + 3] = l3;
        }
        {
            int n  = tid & 127;
            int kb = (tid >> 7) * 16;
#pragma unroll
            for (int i = 0; i < 16; i++) {
                int k = kb + i;
                float v = B[(size_t)(k0 + k) * N + block_col + n];
                __half h, l; split_h(v, h, l);
                BhT[n][k] = h; BlT[n][k] = l;
            }
        }
        __syncthreads();
#pragma unroll
        for (int ks = 0; ks < 2; ks++) {
            const int kk = ks * 16;
            unsigned ah[2][4], al[2][4];
#pragma unroll
            for (int mt = 0; mt < 2; mt++) {
                int r0 = warp_m * 32 + mt * 16 + g;
                ah[mt][0] = *(const unsigned*)&Ah[r0][kk + 2 * t];
                ah[mt][1] = *(const unsigned*)&Ah[r0 + 8][kk + 2 * t];
                ah[mt][2] = *(const unsigned*)&Ah[r0][kk + 2 * t + 8];
                ah[mt][3] = *(const unsigned*)&Ah[r0 + 8][kk + 2 * t + 8];
                al[mt][0] = *(const unsigned*)&Al[r0][kk + 2 * t];
                al[mt][1] = *(const unsigned*)&Al[r0 + 8][kk + 2 * t];
                al[mt][2] = *(const unsigned*)&Al[r0][kk + 2 * t + 8];
                al[mt][3] = *(const unsigned*)&Al[r0 + 8][kk + 2 * t + 8];
            }
#pragma unroll
            for (int nt = 0; nt < 8; nt++) {
                int n0 = warp_n * 64 + nt * 8 + g;
                unsigned bh[2], bl[2];
                bh[0] = *(const unsigned*)&BhT[n0][kk + 2 * t];
                bh[1] = *(const unsigned*)&BhT[n0][kk + 2 * t + 8];
                bl[0] = *(const unsigned*)&BlT[n0][kk + 2 * t];
                bl[1] = *(const unsigned*)&BlT[n0][kk + 2 * t + 8];
#pragma unroll
                for (int mt = 0; mt < 2; mt++) {
                    mma_f16(acc[mt][nt], ah[mt], bl);
                    mma_f16(acc[mt][nt], al[mt], bh);
                    mma_f16(acc[mt][nt], ah[mt], bh);
                }
            }
        }
        __syncthreads();
    }

    const int head = blockIdx.x * 2 + warp_n;
#pragma unroll
    for (int mt = 0; mt < 2; mt++) {
#pragma unroll
        for (int rr = 0; rr < 2; rr++) {
            int grow = block_row + warp_m * 32 + mt * 16 + g + rr * 8;
            bool valid = grow < M;
            float as_p = 0.f, ad_p = 0.f;
#pragma unroll
            for (int nt = 0; nt < 8; nt++) {
                float v0 = acc[mt][nt][rr * 2 + 0];
                float v1 = acc[mt][nt][rr * 2 + 1];
                int col = warp_n * 64 + nt * 8 + 2 * t;
                as_p += v0 * satt_s[col] + v1 * satt_s[col + 1];
                ad_p += v0 * satt_d[col] + v1 * satt_d[col + 1];
                if (valid) {
                    __half2 hv = __floats2half2_rn(v0, v1);
                    *(__half2*)&g_h1h[(size_t)grow * F1 + block_col + col] = hv;
                }
            }
            as_p += __shfl_xor_sync(0xffffffffu, as_p, 1);
            as_p += __shfl_xor_sync(0xffffffffu, as_p, 2);
            ad_p += __shfl_xor_sync(0xffffffffu, ad_p, 1);
            ad_p += __shfl_xor_sync(0xffffffffu, ad_p, 2);
            if (t == 0 && valid) {
                g_as1[grow * HEADS + head] = as_p;
                g_ad1[grow * HEADS + head] = ad_p;
            }
        }
    }
}

// ----------------------------------------------------------------------------
// GEMM2 fused (2xFP16 HMMA, exact fp16 A): h2 = x2h @ W2  (PROVEN r8)
// ----------------------------------------------------------------------------
__global__ void __launch_bounds__(128) gemm2_fused(const float* __restrict__ B,
                                                   const float* __restrict__ att_s,
                                                   const float* __restrict__ att_d) {
    constexpr int M = N_NODES, N = OUT_C, K = F1;
    constexpr int BM = 128, BN = 64, BK = 32;
    constexpr int SKA = BK + 8;
    const __half* A = g_x2h;
    __shared__ __half Ah[BM][SKA];
    __shared__ __half BhT[BN][SKA], BlT[BN][SKA];
    __shared__ float satt_s[BN], satt_d[BN];

    const int tid = threadIdx.x;
    const int lane = tid & 31, warp = tid >> 5;
    const int g = lane >> 2, t = lane & 3;
    const int block_row = blockIdx.y * BM;

    if (tid < BN) {
        satt_s[tid] = att_s[tid];
        satt_d[tid] = att_d[tid];
    }

    float acc[2][8][4];
#pragma unroll
    for (int mt = 0; mt < 2; mt++)
#pragma unroll
        for (int nt = 0; nt < 8; nt++)
#pragma unroll
            for (int q = 0; q < 4; q++) acc[mt][nt][q] = 0.f;

    for (int k0 = 0; k0 < K; k0 += BK) {
#pragma unroll
        for (int it = 0; it < 4; it++) {
            int idx = tid + it * 128;
            int r  = idx >> 2;
            int c8 = idx & 3;
            int gr = block_row + r;
            uint4 v = make_uint4(0u, 0u, 0u, 0u);
            if (gr < M) v = *(const uint4*)(A + (size_t)gr * K + k0 + c8 * 8);
            *(uint4*)&Ah[r][c8 * 8] = v;
        }
        {
            int n  = tid & 63;
            int kb = (tid >> 6) * 16;
#pragma unroll
            for (int i = 0; i < 16; i++) {
                int k = kb + i;
                float v = B[(size_t)(k0 + k) * N + n];
                __half h, l; split_h(v, h, l);
                BhT[n][k] = h; BlT[n][k] = l;
            }
        }
        __syncthreads();
#pragma unroll
        for (int ks = 0; ks < 2; ks++) {
            const int kk = ks * 16;
            unsigned ah[2][4];
#pragma unroll
            for (int mt = 0; mt < 2; mt++) {
                int r0 = warp * 32 + mt * 16 + g;
                ah[mt][0] = *(const unsigned*)&Ah[r0][kk + 2 * t];
                ah[mt][1] = *(const unsigned*)&Ah[r0 + 8][kk + 2 * t];
                ah[mt][2] = *(const unsigned*)&Ah[r0][kk + 2 * t + 8];
                ah[mt][3] = *(const unsigned*)&Ah[r0 + 8][kk + 2 * t + 8];
            }
#pragma unroll
            for (int nt = 0; nt < 8; nt++) {
                int n0 = nt * 8 + g;
                unsigned bh[2], bl[2];
                bh[0] = *(const unsigned*)&BhT[n0][kk + 2 * t];
                bh[1] = *(const unsigned*)&BhT[n0][kk + 2 * t + 8];
                bl[0] = *(const unsigned*)&BlT[n0][kk + 2 * t];
                bl[1] = *(const unsigned*)&BlT[n0][kk + 2 * t + 8];
#pragma unroll
                for (int mt = 0; mt < 2; mt++) {
                    mma_f16(acc[mt][nt], ah[mt], bl);
                    mma_f16(acc[mt][nt], ah[mt], bh);
                }
            }
        }
        __syncthreads();
    }

#pragma unroll
    for (int mt = 0; mt < 2; mt++) {
#pragma unroll
        for (int rr = 0; rr < 2; rr++) {
            int grow = block_row + warp * 32 + mt * 16 + g + rr * 8;
            bool valid = grow < M;
            float as_p = 0.f, ad_p = 0.f;
#pragma unroll
            for (int nt = 0; nt < 8; nt++) {
                float v0 = acc[mt][nt][rr * 2 + 0];
                float v1 = acc[mt][nt][rr * 2 + 1];
                int col = nt * 8 + 2 * t;
                as_p += v0 * satt_s[col] + v1 * satt_s[col + 1];
                ad_p += v0 * satt_d[col] + v1 * satt_d[col + 1];
                if (valid) {
                    __half2 hv = __floats2half2_rn(v0, v1);
                    *(__half2*)&g_h2h[(size_t)grow * OUT_C + col] = hv;
                }
            }
            as_p += __shfl_xor_sync(0xffffffffu, as_p, 1);
            as_p += __shfl_xor_sync(0xffffffffu, as_p, 2);
            ad_p += __shfl_xor_sync(0xffffffffu, ad_p, 1);
            ad_p += __shfl_xor_sync(0xffffffffu, ad_p, 2);
            if (t == 0 && valid) {
                g_as2[grow] = as_p;
                g_ad2[grow] = ad_p;
            }
        }
    }
}

// ----------------------------------------------------------------------------
// Layer-1 aggregation (PROVEN r8): warp per dst node, single-pass softmax,
// fp16 gathers, fp32 accumulation, fp16 x2 output.
// ----------------------------------------------------------------------------
__global__ void agg1_kernel(const float* __restrict__ b1) {
    int t = threadIdx.x;
    int warp = (blockIdx.x * blockDim.x + t) >> 5;
    if (warp >= N_NODES) return;
    int lane = t & 31;
    int d = warp;
    int head = lane >> 3;

    float ad = g_ad1[d * HEADS + head];
    int beg = g_rowptr[d], end = g_rowptr[d + 1];

    float denom = 1e-16f;
    float acc[8] = {0.f, 0.f, 0.f, 0.f, 0.f, 0.f, 0.f, 0.f};
    for (int i = beg; i < end; i++) {
        int s = g_csr_src[i];
        float w = __expf(lrelu(g_as1[s * HEADS + head] + ad));
        denom += w;
        uint4 u = *(const uint4*)&g_h1h[(size_t)s * F1 + lane * 8];
        float2 f0 = __half22float2(*reinterpret_cast<__half2*>(&u.x));
        float2 f1 = __half22float2(*reinterpret_cast<__half2*>(&u.y));
        float2 f2 = __half22float2(*reinterpret_cast<__half2*>(&u.z));
        float2 f3 = __half22float2(*reinterpret_cast<__half2*>(&u.w));
        acc[0] += w * f0.x; acc[1] += w * f0.y;
        acc[2] += w * f1.x; acc[3] += w * f1.y;
        acc[4] += w * f2.x; acc[5] += w * f2.y;
        acc[6] += w * f3.x; acc[7] += w * f3.y;
    }
    {   // self loop
        float w = __expf(lrelu(g_as1[d * HEADS + head] + ad));
        denom += w;
        uint4 u = *(const uint4*)&g_h1h[(size_t)d * F1 + lane * 8];
        float2 f0 = __half22float2(*reinterpret_cast<__half2*>(&u.x));
        float2 f1 = __half22float2(*reinterpret_cast<__half2*>(&u.y));
        float2 f2 = __half22float2(*reinterpret_cast<__half2*>(&u.z));
        float2 f3 = __half22float2(*reinterpret_cast<__half2*>(&u.w));
        acc[0] += w * f0.x; acc[1] += w * f0.y;
        acc[2] += w * f1.x; acc[3] += w * f1.y;
        acc[4] += w * f2.x; acc[5] += w * f2.y;
        acc[6] += w * f3.x; acc[7] += w * f3.y;
    }
    float inv = 1.f / denom;
    int cb = lane * 8;
    __half hbuf[8];
#pragma unroll
    for (int j = 0; j < 8; j++)
        hbuf[j] = __float2half(fmaxf(acc[j] * inv + b1[cb + j], 0.f));
    *(uint4*)&g_x2h[(size_t)d * F1 + cb] = *(uint4*)hbuf;
}

// ----------------------------------------------------------------------------
// Layer-2 aggregation (heads=1) + bias + relu + global mean-pool accumulation.
// ----------------------------------------------------------------------------
__global__ void agg2_pool_kernel(const float* __restrict__ b2) {
    __shared__ float sp[OUT_C];
    int t = threadIdx.x;
    if (t < OUT_C) sp[t] = 0.f;
    __syncthreads();

    int warp = (blockIdx.x * blockDim.x + t) >> 5;
    int lane = t & 31;
    if (warp < N_NODES) {
        int d = warp;
        float ad = g_ad2[d];
        int beg = g_rowptr[d], end = g_rowptr[d + 1];

        float denom = 1e-16f;
        float a0 = 0.f, a1 = 0.f;
        for (int i = beg; i < end; i++) {
            int s = g_csr_src[i];
            float w = __expf(lrelu(g_as2[s] + ad));
            denom += w;
            a0 += w * __half2float(g_h2h[(size_t)s * OUT_C + lane]);
            a1 += w * __half2float(g_h2h[(size_t)s * OUT_C + 32 + lane]);
        }
        {
            float w = __expf(lrelu(g_as2[d] + ad));
            denom += w;
            a0 += w * __half2float(g_h2h[(size_t)d * OUT_C + lane]);
            a1 += w * __half2float(g_h2h[(size_t)d * OUT_C + 32 + lane]);
        }
        float inv = 1.f / denom;
        float v0 = fmaxf(a0 * inv + b2[lane], 0.f);
        float v1 = fmaxf(a1 * inv + b2[32 + lane], 0.f);
        atomicAdd(&sp[lane], v0);
        atomicAdd(&sp[32 + lane], v1);
    }
    __syncthreads();
    if (t < OUT_C) atomicAdd(&g_pooled[t], sp[t]);
}

// ----------------------------------------------------------------------------
// Final: mean-pool scale, FC to 40 classes, log_softmax
// ----------------------------------------------------------------------------
__global__ void final_kernel(const float* __restrict__ fc_w,
                             const float* __restrict__ fc_b,
                             float* __restrict__ out) {
    __shared__ float p[OUT_C];
    __shared__ float lg[NUM_CLASSES];
    __shared__ float lse_sh;
    int t = threadIdx.x;  // 64 threads
    p[t] = g_pooled[t] * (1.0f / (float)N_NODES);
    __syncthreads();
    if (t < NUM_CLASSES) {
        float s = fc_b[t];
#pragma unroll
        for (int c = 0; c < OUT_C; c++) s += p[c] * fc_w[c * NUM_CLASSES + t];
        lg[t] = s;
    }
    __syncthreads();
    if (t == 0) {
        float mx = lg[0];
        for (int j = 1; j < NUM_CLASSES; j++) mx = fmaxf(mx, lg[j]);
        float se = 0.f;
        for (int j = 0; j < NUM_CLASSES; j++) se += expf(lg[j] - mx);
        lse_sh = mx + logf(se);
    }
    __syncthreads();
    if (t < NUM_CLASSES) out[t] = lg[t] - lse_sh;
}

// ----------------------------------------------------------------------------
// launch: CSR build (side stream) runs concurrently with gemm1 (main stream).
// Fork-join via events — the standard capture-compatible pattern. Stream and
// events are created once; the captured graph is identical on every call
// (deterministic: same inputs -> same work).
// ----------------------------------------------------------------------------
extern "C" void kernel_launch(void* const* d_in, const int* in_sizes, int n_in,
                              void* d_out, int out_size) {
    const float* x      = (const float*)d_in[0];
    const void*  ei     = d_in[1];
    const float* W1     = (const float*)d_in[2];
    const float* att_s1 = (const float*)d_in[3];
    const float* att_d1 = (const float*)d_in[4];
    const float* b1     = (const float*)d_in[5];
    const float* W2     = (const float*)d_in[6];
    const float* att_s2 = (const float*)d_in[7];
    const float* att_d2 = (const float*)d_in[8];
    const float* b2     = (const float*)d_in[9];
    const float* fc_w   = (const float*)d_in[10];
    const float* fc_b   = (const float*)d_in[11];
    float* out = (float*)d_out;

    int E = in_sizes[1] / 2;
    if (E > E_MAX) E = E_MAX;

    const int WARPS_PER_BLOCK = 8;
    const int nodeBlocks = (N_NODES + WARPS_PER_BLOCK - 1) / WARPS_PER_BLOCK;
    const int mBlocks = (N_NODES + 127) / 128;

    static cudaStream_t s_side = nullptr;
    static cudaEvent_t  ev_fork = nullptr, ev_join = nullptr;
    if (s_side == nullptr) {
        cudaStreamCreateWithFlags(&s_side, cudaStreamNonBlocking);
        cudaEventCreateWithFlags(&ev_fork, cudaEventDisableTiming);
        cudaEventCreateWithFlags(&ev_join, cudaEventDisableTiming);
    }

    // Fork: CSR-build chain on side stream
    cudaEventRecord(ev_fork, 0);
    cudaStreamWaitEvent(s_side, ev_fork, 0);

    init_detect_kernel<<<(N_NODES + 256) / 256, 256, 0, s_side>>>((const int*)ei);
    convert_count_kernel<<<(E + 255) / 256, 256, 0, s_side>>>(ei, E);
    scan1_kernel<<<SCAN_NBLK, SCAN_BLOCK, 0, s_side>>>();
    scan2_kernel<<<1, 64, 0, s_side>>>();
    scan3_kernel<<<SCAN_NBLK, SCAN_BLOCK, 0, s_side>>>();
    fill_kernel<<<(E + 255) / 256, 256, 0, s_side>>>(E);
    cudaEventRecord(ev_join, s_side);

    // Concurrent on main stream: layer-1 GEMM (independent of CSR)
    gemm1_fused<<<dim3(F1 / 128, mBlocks), 256>>>(x, W1, att_s1, att_d1);

    // Join: agg1 needs both CSR and gemm1
    cudaStreamWaitEvent(0, ev_join, 0);

    agg1_kernel<<<nodeBlocks, 256>>>(b1);
    gemm2_fused<<<dim3(1, mBlocks), 128>>>(W2, att_s2, att_d2);
    agg2_pool_kernel<<<nodeBlocks, 256>>>(b2);
    final_kernel<<<1, 64>>>(fc_w, fc_b, out);
}

// round 10
// speedup vs baseline: 2.4002x; 1.0638x over previous
#include <cuda_runtime.h>
#include <cuda_bf16.h>
#include <cuda_fp16.h>
#include <cuda_fp8.h>
#include <math.h>

// Problem constants (fixed by the reference)
#define N_NODES 50000
#define E_MAX   800000
#define IN_C    128
#define HID     64
#define HEADS   4
#define F1      (HEADS*HID)   // 256
#define OUT_C   64
#define NUM_CLASSES 40

#define SCAN_BLOCK 1024
#define SCAN_NBLK  ((N_NODES + SCAN_BLOCK - 1) / SCAN_BLOCK)   // 49

// ----------------------------------------------------------------------------
// Scratch (device globals: allocation-free per harness rules)
// ----------------------------------------------------------------------------
__device__ unsigned char g_h1q[(size_t)N_NODES * F1];  // layer-1 features, fp8 e4m3
__device__ __half g_x2h[(size_t)N_NODES * F1];         // layer-1 GAT output, fp16
__device__ __half g_h2h[(size_t)N_NODES * OUT_C];      // layer-2 features, fp16
__device__ __half g_w1hT[(size_t)F1 * IN_C];           // W1^T hi  [n][k]
__device__ __half g_w1lT[(size_t)F1 * IN_C];           // W1^T lo
__device__ __half g_w2hT[(size_t)OUT_C * F1];          // W2^T hi
__device__ __half g_w2lT[(size_t)OUT_C * F1];          // W2^T lo
__device__ float  g_as1[N_NODES * HEADS];
__device__ float  g_ad1[N_NODES * HEADS];
__device__ float  g_as2[N_NODES];
__device__ float  g_ad2[N_NODES];
__device__ int    g_counts[N_NODES + 1];
__device__ int    g_rowptr[N_NODES + 1];
__device__ int    g_cursor[N_NODES];
__device__ int    g_src32[E_MAX];
__device__ int    g_dst32[E_MAX];
__device__ int    g_csr_src[E_MAX];
__device__ int    g_blksum[SCAN_NBLK];
__device__ int    g_blkoff[SCAN_NBLK];
__device__ float  g_pooled[OUT_C];
__device__ int    g_is64;

__device__ __forceinline__ float lrelu(float v) { return v > 0.f ? v : 0.2f * v; }

__device__ __forceinline__ void split_h(float v, __half& hi, __half& lo) {
    hi = __float2half(v);
    lo = __float2half(v - __half2float(hi));
}

__device__ __forceinline__ float2 fp8x2_to_float2(unsigned short v) {
    __half2_raw hr = __nv_cvt_fp8x2_to_halfraw2((__nv_fp8x2_storage_t)v, __NV_E4M3);
    return __half22float2(*reinterpret_cast<__half2*>(&hr));
}

// m16n8k16 fp16 MMA, fp32 accumulate
__device__ __forceinline__ void mma_f16(float* c, const unsigned* a, const unsigned* b) {
    asm volatile(
        "mma.sync.aligned.m16n8k16.row.col.f32.f16.f16.f32 "
        "{%0,%1,%2,%3}, {%4,%5,%6,%7}, {%8,%9}, {%0,%1,%2,%3};\n"
        : "+f"(c[0]), "+f"(c[1]), "+f"(c[2]), "+f"(c[3])
        : "r"(a[0]), "r"(a[1]), "r"(a[2]), "r"(a[3]), "r"(b[0]), "r"(b[1]));
}

// ----------------------------------------------------------------------------
// W pre-split + transpose: W1[k][n] -> w1{h,l}T[n][k]; W2 likewise. Tiny.
// ----------------------------------------------------------------------------
__global__ void wsplit_kernel(const float* __restrict__ W1,
                              const float* __restrict__ W2) {
    int i = blockIdx.x * blockDim.x + threadIdx.x;
    if (i < IN_C * F1) {
        int k = i / F1, n = i % F1;
        __half h, l; split_h(W1[i], h, l);
        g_w1hT[(size_t)n * IN_C + k] = h;
        g_w1lT[(size_t)n * IN_C + k] = l;
    }
    if (i < F1 * OUT_C) {
        int k = i / OUT_C, n = i % OUT_C;
        __half h, l; split_h(W2[i], h, l);
        g_w2hT[(size_t)n * F1 + k] = h;
        g_w2lT[(size_t)n * F1 + k] = l;
    }
}

// ----------------------------------------------------------------------------
// 0+1) init (zero counts + pooled) and int64/int32 detection, one launch
// ----------------------------------------------------------------------------
__global__ void init_detect_kernel(const int* __restrict__ ei) {
    int i = blockIdx.x * blockDim.x + threadIdx.x;
    if (i < N_NODES + 1) g_counts[i] = 0;
    if (i < OUT_C)       g_pooled[i] = 0.f;
    if (blockIdx.x == 0) {
        __shared__ int any;
        if (threadIdx.x == 0) any = 0;
        __syncthreads();
        for (int j = threadIdx.x; j < 4096; j += blockDim.x) {
            if (ei[2 * j + 1] != 0) any = 1;
        }
        __syncthreads();
        if (threadIdx.x == 0) g_is64 = (any == 0) ? 1 : 0;
    }
}

// ----------------------------------------------------------------------------
// 2) convert to int32 + count in-degrees
// ----------------------------------------------------------------------------
__global__ void convert_count_kernel(const void* __restrict__ ei, int E) {
    int e = blockIdx.x * blockDim.x + threadIdx.x;
    if (e >= E) return;
    int s, d;
    if (g_is64) {
        const long long* p = (const long long*)ei;
        s = (int)p[e]; d = (int)p[E + e];
    } else {
        const int* p = (const int*)ei;
        s = p[e]; d = p[E + e];
    }
    g_src32[e] = s;
    g_dst32[e] = d;
    atomicAdd(&g_counts[d], 1);
}

// ----------------------------------------------------------------------------
// 3) parallel exclusive scan of g_counts -> g_rowptr / g_cursor  (PROVEN r4)
// ----------------------------------------------------------------------------
__global__ void __launch_bounds__(SCAN_BLOCK) scan1_kernel() {
    int i = blockIdx.x * SCAN_BLOCK + threadIdx.x;
    int v = (i < N_NODES) ? g_counts[i] : 0;
    __shared__ int sh[32];
    int lane = threadIdx.x & 31, w = threadIdx.x >> 5;
#pragma unroll
    for (int o = 16; o; o >>= 1) v += __shfl_xor_sync(~0u, v, o);
    if (lane == 0) sh[w] = v;
    __syncthreads();
    if (w == 0) {
        int s = sh[lane];
#pragma unroll
        for (int o = 16; o; o >>= 1) s += __shfl_xor_sync(~0u, s, o);
        if (lane == 0) g_blksum[blockIdx.x] = s;
    }
}

__global__ void scan2_kernel() {
    __shared__ int s[64];
    int t = threadIdx.x;
    int v = (t < SCAN_NBLK) ? g_blksum[t] : 0;
    s[t] = v;
    __syncthreads();
#pragma unroll
    for (int o = 1; o < 64; o <<= 1) {
        int u = (t >= o) ? s[t - o] : 0;
        __syncthreads();
        s[t] += u;
        __syncthreads();
    }
    if (t < SCAN_NBLK) g_blkoff[t] = s[t] - v;
    if (t == SCAN_NBLK - 1) g_rowptr[N_NODES] = s[t];
}

__global__ void __launch_bounds__(SCAN_BLOCK) scan3_kernel() {
    int b = blockIdx.x, t = threadIdx.x;
    int i = b * SCAN_BLOCK + t;
    int v = (i < N_NODES) ? g_counts[i] : 0;
    int lane = t & 31, w = t >> 5;
    int inc = v;
#pragma unroll
    for (int o = 1; o < 32; o <<= 1) {
        int u = __shfl_up_sync(~0u, inc, o);
        if (lane >= o) inc += u;
    }
    __shared__ int wsum[32];
    if (lane == 31) wsum[w] = inc;
    __syncthreads();
    if (w == 0) {
        int s = wsum[lane];
#pragma unroll
        for (int o = 1; o < 32; o <<= 1) {
            int u = __shfl_up_sync(~0u, s, o);
            if (lane >= o) s += u;
        }
        wsum[lane] = s;
    }
    __syncthreads();
    int exc = inc - v + (w > 0 ? wsum[w - 1] : 0) + g_blkoff[b];
    if (i < N_NODES) {
        g_rowptr[i] = exc;
        g_cursor[i] = exc;
    }
}

// ----------------------------------------------------------------------------
// 4) fill CSR (src indices grouped by dst)
// ----------------------------------------------------------------------------
__global__ void fill_kernel(int E) {
    int e = blockIdx.x * blockDim.x + threadIdx.x;
    if (e >= E) return;
    int pos = atomicAdd(&g_cursor[g_dst32[e]], 1);
    g_csr_src[pos] = g_src32[e];
}

// ----------------------------------------------------------------------------
// GEMM1 fused (3xFP16 HMMA): h1 = x @ W1  (50000x128 @ 128x256)
// B tiles pre-split/transposed (vector loads). Epilogue: fp8 h1 store +
// alpha logits from fp32 accumulators.
// ----------------------------------------------------------------------------
__global__ void __launch_bounds__(256) gemm1_fused(const float* __restrict__ A,
                                                   const float* __restrict__ att_s,
                                                   const float* __restrict__ att_d) {
    constexpr int M = N_NODES, K = IN_C;
    constexpr int BM = 128, BN = 128, BK = 32;
    constexpr int SKA = BK + 8;
    __shared__ __half Ah[BM][SKA], Al[BM][SKA];
    __shared__ __half BhT[BN][SKA], BlT[BN][SKA];
    __shared__ float satt_s[BN], satt_d[BN];

    const int tid = threadIdx.x;
    const int lane = tid & 31, warp = tid >> 5;
    const int g = lane >> 2, t = lane & 3;
    const int warp_m = warp & 3;
    const int warp_n = warp >> 2;
    const int block_row = blockIdx.y * BM;
    const int block_col = blockIdx.x * BN;

    if (tid < BN) {
        satt_s[tid] = att_s[block_col + tid];
        satt_d[tid] = att_d[block_col + tid];
    }

    float acc[2][8][4];
#pragma unroll
    for (int mt = 0; mt < 2; mt++)
#pragma unroll
        for (int nt = 0; nt < 8; nt++)
#pragma unroll
            for (int q = 0; q < 4; q++) acc[mt][nt][q] = 0.f;

    for (int k0 = 0; k0 < K; k0 += BK) {
        // A tile 128x32 fp32 -> hi/lo halves (in-kernel split)
#pragma unroll
        for (int it = 0; it < 4; it++) {
            int idx = tid + it * 256;
            int r  = idx >> 3;
            int c4 = idx & 7;
            int gr = block_row + r;
            float4 v = make_float4(0.f, 0.f, 0.f, 0.f);
            if (gr < M) v = *(const float4*)(A + (size_t)gr * K + k0 + c4 * 4);
            __half h0, l0, h1, l1, h2, l2, h3, l3;
            split_h(v.x, h0, l0); split_h(v.y, h1, l1);
            split_h(v.z, h2, l2); split_h(v.w, h3, l3);
            int c = c4 * 4;
            Ah[r][c + 0] = h0; Ah[r][c + 1] = h1; Ah[r][c + 2] = h2; Ah[r][c + 3] = h3;
            Al[r][c + 0] = l0; Al[r][c + 1] = l1; Al[r][c + 2] = l2; Al[r][c + 3] = l3;
        }
        // B tiles: pre-split, pre-transposed -> pure uint4 copies
#pragma unroll
        for (int it = 0; it < 2; it++) {
            int idx = tid + it * 256;
            int n = idx >> 2, c8 = idx & 3;
            *(uint4*)&BhT[n][c8 * 8] =
                *(const uint4*)&g_w1hT[(size_t)(block_col + n) * K + k0 + c8 * 8];
        }
#pragma unroll
        for (int it = 0; it < 2; it++) {
            int idx = tid + it * 256;
            int n = idx >> 2, c8 = idx & 3;
            *(uint4*)&BlT[n][c8 * 8] =
                *(const uint4*)&g_w1lT[(size_t)(block_col + n) * K + k0 + c8 * 8];
        }
        __syncthreads();
#pragma unroll
        for (int ks = 0; ks < 2; ks++) {
            const int kk = ks * 16;
            unsigned ah[2][4], al[2][4];
#pragma unroll
            for (int mt = 0; mt < 2; mt++) {
                int r0 = warp_m * 32 + mt * 16 + g;
                ah[mt][0] = *(const unsigned*)&Ah[r0][kk + 2 * t];
                ah[mt][1] = *(const unsigned*)&Ah[r0 + 8][kk + 2 * t];
                ah[mt][2] = *(const unsigned*)&Ah[r0][kk + 2 * t + 8];
                ah[mt][3] = *(const unsigned*)&Ah[r0 + 8][kk + 2 * t + 8];
                al[mt][0] = *(const unsigned*)&Al[r0][kk + 2 * t];
                al[mt][1] = *(const unsigned*)&Al[r0 + 8][kk + 2 * t];
                al[mt][2] = *(const unsigned*)&Al[r0][kk + 2 * t + 8];
                al[mt][3] = *(const unsigned*)&Al[r0 + 8][kk + 2 * t + 8];
            }
#pragma unroll
            for (int nt = 0; nt < 8; nt++) {
                int n0 = warp_n * 64 + nt * 8 + g;
                unsigned bh[2], bl[2];
                bh[0] = *(const unsigned*)&BhT[n0][kk + 2 * t];
                bh[1] = *(const unsigned*)&BhT[n0][kk + 2 * t + 8];
                bl[0] = *(const unsigned*)&BlT[n0][kk + 2 * t];
                bl[1] = *(const unsigned*)&BlT[n0][kk + 2 * t + 8];
#pragma unroll
                for (int mt = 0; mt < 2; mt++) {
                    mma_f16(acc[mt][nt], ah[mt], bl);
                    mma_f16(acc[mt][nt], al[mt], bh);
                    mma_f16(acc[mt][nt], ah[mt], bh);
                }
            }
        }
        __syncthreads();
    }

    const int head = blockIdx.x * 2 + warp_n;
#pragma unroll
    for (int mt = 0; mt < 2; mt++) {
#pragma unroll
        for (int rr = 0; rr < 2; rr++) {
            int grow = block_row + warp_m * 32 + mt * 16 + g + rr * 8;
            bool valid = grow < M;
            float as_p = 0.f, ad_p = 0.f;
#pragma unroll
            for (int nt = 0; nt < 8; nt++) {
                float v0 = acc[mt][nt][rr * 2 + 0];
                float v1 = acc[mt][nt][rr * 2 + 1];
                int col = warp_n * 64 + nt * 8 + 2 * t;
                as_p += v0 * satt_s[col] + v1 * satt_s[col + 1];
                ad_p += v0 * satt_d[col] + v1 * satt_d[col + 1];
                if (valid) {
                    __nv_fp8x2_storage_t p = __nv_cvt_float2_to_fp8x2(
                        make_float2(v0, v1), __NV_SATFINITE, __NV_E4M3);
                    *(unsigned short*)&g_h1q[(size_t)grow * F1 + block_col + col] =
                        (unsigned short)p;
                }
            }
            as_p += __shfl_xor_sync(0xffffffffu, as_p, 1);
            as_p += __shfl_xor_sync(0xffffffffu, as_p, 2);
            ad_p += __shfl_xor_sync(0xffffffffu, ad_p, 1);
            ad_p += __shfl_xor_sync(0xffffffffu, ad_p, 2);
            if (t == 0 && valid) {
                g_as1[grow * HEADS + head] = as_p;
                g_ad1[grow * HEADS + head] = ad_p;
            }
        }
    }
}

// ----------------------------------------------------------------------------
// GEMM2 fused (2xFP16 HMMA, exact fp16 A): h2 = x2h @ W2
// B pre-split/transposed.
// ----------------------------------------------------------------------------
__global__ void __launch_bounds__(128) gemm2_fused(const float* __restrict__ att_s,
                                                   const float* __restrict__ att_d) {
    constexpr int M = N_NODES, K = F1;
    constexpr int BM = 128, BN = 64, BK = 32;
    constexpr int SKA = BK + 8;
    const __half* A = g_x2h;
    __shared__ __half Ah[BM][SKA];
    __shared__ __half BhT[BN][SKA], BlT[BN][SKA];
    __shared__ float satt_s[BN], satt_d[BN];

    const int tid = threadIdx.x;
    const int lane = tid & 31, warp = tid >> 5;
    const int g = lane >> 2, t = lane & 3;
    const int block_row = blockIdx.y * BM;

    if (tid < BN) {
        satt_s[tid] = att_s[tid];
        satt_d[tid] = att_d[tid];
    }

    float acc[2][8][4];
#pragma unroll
    for (int mt = 0; mt < 2; mt++)
#pragma unroll
        for (int nt = 0; nt < 8; nt++)
#pragma unroll
            for (int q = 0; q < 4; q++) acc[mt][nt][q] = 0.f;

    for (int k0 = 0; k0 < K; k0 += BK) {
#pragma unroll
        for (int it = 0; it < 4; it++) {
            int idx = tid + it * 128;
            int r  = idx >> 2;
            int c8 = idx & 3;
            int gr = block_row + r;
            uint4 v = make_uint4(0u, 0u, 0u, 0u);
            if (gr < M) v = *(const uint4*)(A + (size_t)gr * K + k0 + c8 * 8);
            *(uint4*)&Ah[r][c8 * 8] = v;
        }
#pragma unroll
        for (int it = 0; it < 2; it++) {
            int idx = tid + it * 128;
            int n = idx >> 2, c8 = idx & 3;
            *(uint4*)&BhT[n][c8 * 8] =
                *(const uint4*)&g_w2hT[(size_t)n * K + k0 + c8 * 8];
        }
#pragma unroll
        for (int it = 0; it < 2; it++) {
            int idx = tid + it * 128;
            int n = idx >> 2, c8 = idx & 3;
            *(uint4*)&BlT[n][c8 * 8] =
                *(const uint4*)&g_w2lT[(size_t)n * K + k0 + c8 * 8];
        }
        __syncthreads();
#pragma unroll
        for (int ks = 0; ks < 2; ks++) {
            const int kk = ks * 16;
            unsigned ah[2][4];
#pragma unroll
            for (int mt = 0; mt < 2; mt++) {
                int r0 = warp * 32 + mt * 16 + g;
                ah[mt][0] = *(const unsigned*)&Ah[r0][kk + 2 * t];
                ah[mt][1] = *(const unsigned*)&Ah[r0 + 8][kk + 2 * t];
                ah[mt][2] = *(const unsigned*)&Ah[r0][kk + 2 * t + 8];
                ah[mt][3] = *(const unsigned*)&Ah[r0 + 8][kk + 2 * t + 8];
            }
#pragma unroll
            for (int nt = 0; nt < 8; nt++) {
                int n0 = nt * 8 + g;
                unsigned bh[2], bl[2];
                bh[0] = *(const unsigned*)&BhT[n0][kk + 2 * t];
                bh[1] = *(const unsigned*)&BhT[n0][kk + 2 * t + 8];
                bl[0] = *(const unsigned*)&BlT[n0][kk + 2 * t];
                bl[1] = *(const unsigned*)&BlT[n0][kk + 2 * t + 8];
#pragma unroll
                for (int mt = 0; mt < 2; mt++) {
                    mma_f16(acc[mt][nt], ah[mt], bl);
                    mma_f16(acc[mt][nt], ah[mt], bh);
                }
            }
        }
        __syncthreads();
    }

#pragma unroll
    for (int mt = 0; mt < 2; mt++) {
#pragma unroll
        for (int rr = 0; rr < 2; rr++) {
            int grow = block_row + warp * 32 + mt * 16 + g + rr * 8;
            bool valid = grow < M;
            float as_p = 0.f, ad_p = 0.f;
#pragma unroll
            for (int nt = 0; nt < 8; nt++) {
                float v0 = acc[mt][nt][rr * 2 + 0];
                float v1 = acc[mt][nt][rr * 2 + 1];
                int col = nt * 8 + 2 * t;
                as_p += v0 * satt_s[col] + v1 * satt_s[col + 1];
                ad_p += v0 * satt_d[col] + v1 * satt_d[col + 1];
                if (valid) {
                    __half2 hv = __floats2half2_rn(v0, v1);
                    *(__half2*)&g_h2h[(size_t)grow * OUT_C + col] = hv;
                }
            }
            as_p += __shfl_xor_sync(0xffffffffu, as_p, 1);
            as_p += __shfl_xor_sync(0xffffffffu, as_p, 2);
            ad_p += __shfl_xor_sync(0xffffffffu, ad_p, 1);
            ad_p += __shfl_xor_sync(0xffffffffu, ad_p, 2);
            if (t == 0 && valid) {
                g_as2[grow] = as_p;
                g_ad2[grow] = ad_p;
            }
        }
    }
}

// ----------------------------------------------------------------------------
// Layer-1 aggregation: warp per dst node, single-pass softmax, FP8 gathers
// (8 B/lane/edge), fp32 accumulation, fp16 x2 output. Logits stay fp32-exact.
// ----------------------------------------------------------------------------
__global__ void agg1_kernel(const float* __restrict__ b1) {
    int t = threadIdx.x;
    int warp = (blockIdx.x * blockDim.x + t) >> 5;
    if (warp >= N_NODES) return;
    int lane = t & 31;
    int d = warp;
    int head = lane >> 3;

    float ad = g_ad1[d * HEADS + head];
    int beg = g_rowptr[d], end = g_rowptr[d + 1];

    float denom = 1e-16f;
    float acc[8] = {0.f, 0.f, 0.f, 0.f, 0.f, 0.f, 0.f, 0.f};
    for (int i = beg; i < end; i++) {
        int s = g_csr_src[i];
        float w = __expf(lrelu(g_as1[s * HEADS + head] + ad));
        denom += w;
        uint2 u = *(const uint2*)&g_h1q[(size_t)s * F1 + lane * 8];
        float2 f0 = fp8x2_to_float2((unsigned short)(u.x & 0xffffu));
        float2 f1 = fp8x2_to_float2((unsigned short)(u.x >> 16));
        float2 f2 = fp8x2_to_float2((unsigned short)(u.y & 0xffffu));
        float2 f3 = fp8x2_to_float2((unsigned short)(u.y >> 16));
        acc[0] += w * f0.x; acc[1] += w * f0.y;
        acc[2] += w * f1.x; acc[3] += w * f1.y;
        acc[4] += w * f2.x; acc[5] += w * f2.y;
        acc[6] += w * f3.x; acc[7] += w * f3.y;
    }
    {   // self loop
        float w = __expf(lrelu(g_as1[d * HEADS + head] + ad));
        denom += w;
        uint2 u = *(const uint2*)&g_h1q[(size_t)d * F1 + lane * 8];
        float2 f0 = fp8x2_to_float2((unsigned short)(u.x & 0xffffu));
        float2 f1 = fp8x2_to_float2((unsigned short)(u.x >> 16));
        float2 f2 = fp8x2_to_float2((unsigned short)(u.y & 0xffffu));
        float2 f3 = fp8x2_to_float2((unsigned short)(u.y >> 16));
        acc[0] += w * f0.x; acc[1] += w * f0.y;
        acc[2] += w * f1.x; acc[3] += w * f1.y;
        acc[4] += w * f2.x; acc[5] += w * f2.y;
        acc[6] += w * f3.x; acc[7] += w * f3.y;
    }
    float inv = 1.f / denom;
    int cb = lane * 8;
    __half hbuf[8];
#pragma unroll
    for (int j = 0; j < 8; j++)
        hbuf[j] = __float2half(fmaxf(acc[j] * inv + b1[cb + j], 0.f));
    *(uint4*)&g_x2h[(size_t)d * F1 + cb] = *(uint4*)hbuf;
}

// ----------------------------------------------------------------------------
// Layer-2 aggregation (heads=1) + bias + relu + global mean-pool accumulation.
// ----------------------------------------------------------------------------
__global__ void agg2_pool_kernel(const float* __restrict__ b2) {
    __shared__ float sp[OUT_C];
    int t = threadIdx.x;
    if (t < OUT_C) sp[t] = 0.f;
    __syncthreads();

    int warp = (blockIdx.x * blockDim.x + t) >> 5;
    int lane = t & 31;
    if (warp < N_NODES) {
        int d = warp;
        float ad = g_ad2[d];
        int beg = g_rowptr[d], end = g_rowptr[d + 1];

        float denom = 1e-16f;
        float a0 = 0.f, a1 = 0.f;
        for (int i = beg; i < end; i++) {
            int s = g_csr_src[i];
            float w = __expf(lrelu(g_as2[s] + ad));
            denom += w;
            a0 += w * __half2float(g_h2h[(size_t)s * OUT_C + lane]);
            a1 += w * __half2float(g_h2h[(size_t)s * OUT_C + 32 + lane]);
        }
        {
            float w = __expf(lrelu(g_as2[d] + ad));
            denom += w;
            a0 += w * __half2float(g_h2h[(size_t)d * OUT_C + lane]);
            a1 += w * __half2float(g_h2h[(size_t)d * OUT_C + 32 + lane]);
        }
        float inv = 1.f / denom;
        float v0 = fmaxf(a0 * inv + b2[lane], 0.f);
        float v1 = fmaxf(a1 * inv + b2[32 + lane], 0.f);
        atomicAdd(&sp[lane], v0);
        atomicAdd(&sp[32 + lane], v1);
    }
    __syncthreads();
    if (t < OUT_C) atomicAdd(&g_pooled[t], sp[t]);
}

// ----------------------------------------------------------------------------
// Final: mean-pool scale, FC to 40 classes, log_softmax
// ----------------------------------------------------------------------------
__global__ void final_kernel(const float* __restrict__ fc_w,
                             const float* __restrict__ fc_b,
                             float* __restrict__ out) {
    __shared__ float p[OUT_C];
    __shared__ float lg[NUM_CLASSES];
    __shared__ float lse_sh;
    int t = threadIdx.x;  // 64 threads
    p[t] = g_pooled[t] * (1.0f / (float)N_NODES);
    __syncthreads();
    if (t < NUM_CLASSES) {
        float s = fc_b[t];
#pragma unroll
        for (int c = 0; c < OUT_C; c++) s += p[c] * fc_w[c * NUM_CLASSES + t];
        lg[t] = s;
    }
    __syncthreads();
    if (t == 0) {
        float mx = lg[0];
        for (int j = 1; j < NUM_CLASSES; j++) mx = fmaxf(mx, lg[j]);
        float se = 0.f;
        for (int j = 0; j < NUM_CLASSES; j++) se += expf(lg[j] - mx);
        lse_sh = mx + logf(se);
    }
    __syncthreads();
    if (t < NUM_CLASSES) out[t] = lg[t] - lse_sh;
}

// ----------------------------------------------------------------------------
// launch: CSR build (side stream) overlaps wsplit+gemm1 (main stream).
// ----------------------------------------------------------------------------
extern "C" void kernel_launch(void* const* d_in, const int* in_sizes, int n_in,
                              void* d_out, int out_size) {
    const float* x      = (const float*)d_in[0];
    const void*  ei     = d_in[1];
    const float* W1     = (const float*)d_in[2];
    const float* att_s1 = (const float*)d_in[3];
    const float* att_d1 = (const float*)d_in[4];
    const float* b1     = (const float*)d_in[5];
    const float* W2     = (const float*)d_in[6];
    const float* att_s2 = (const float*)d_in[7];
    const float* att_d2 = (const float*)d_in[8];
    const float* b2     = (const float*)d_in[9];
    const float* fc_w   = (const float*)d_in[10];
    const float* fc_b   = (const float*)d_in[11];
    float* out = (float*)d_out;

    int E = in_sizes[1] / 2;
    if (E > E_MAX) E = E_MAX;

    const int WARPS_PER_BLOCK = 8;
    const int nodeBlocks = (N_NODES + WARPS_PER_BLOCK - 1) / WARPS_PER_BLOCK;
    const int mBlocks = (N_NODES + 127) / 128;

    static cudaStream_t s_side = nullptr;
    static cudaEvent_t  ev_fork = nullptr, ev_join = nullptr;
    if (s_side == nullptr) {
        cudaStreamCreateWithFlags(&s_side, cudaStreamNonBlocking);
        cudaEventCreateWithFlags(&ev_fork, cudaEventDisableTiming);
        cudaEventCreateWithFlags(&ev_join, cudaEventDisableTiming);
    }

    // Fork: CSR-build chain on side stream
    cudaEventRecord(ev_fork, 0);
    cudaStreamWaitEvent(s_side, ev_fork, 0);

    init_detect_kernel<<<(N_NODES + 256) / 256, 256, 0, s_side>>>((const int*)ei);
    convert_count_kernel<<<(E + 255) / 256, 256, 0, s_side>>>(ei, E);
    scan1_kernel<<<SCAN_NBLK, SCAN_BLOCK, 0, s_side>>>();
    scan2_kernel<<<1, 64, 0, s_side>>>();
    scan3_kernel<<<SCAN_NBLK, SCAN_BLOCK, 0, s_side>>>();
    fill_kernel<<<(E + 255) / 256, 256, 0, s_side>>>(E);
    cudaEventRecord(ev_join, s_side);

    // Concurrent on main stream: weight split + layer-1 GEMM
    wsplit_kernel<<<(IN_C * F1 + 255) / 256, 256>>>(W1, W2);
    gemm1_fused<<<dim3(F1 / 128, mBlocks), 256>>>(x, att_s1, att_d1);

    // Join: agg1 needs both CSR and gemm1
    cudaStreamWaitEvent(0, ev_join, 0);

    agg1_kernel<<<nodeBlocks, 256>>>(b1);
    gemm2_fused<<<dim3(1, mBlocks), 128>>>(att_s2, att_d2);
    agg2_pool_kernel<<<nodeBlocks, 256>>>(b2);
    final_kernel<<<1, 64>>>(fc_w, fc_b, out);
}